// round 7
// baseline (speedup 1.0000x reference)
#include <cuda_runtime.h>
#include <cuda_fp16.h>
#include <cstdint>

#define MAXN 50000
#define MAXE 800000
#define HID 128
#define FULLMASK 0xffffffffu

// ---- static scratch (no allocations allowed) ----
__device__ float  g_buf0[(size_t)MAXN * HID];   // fp32 aggregate outputs
__device__ __half g_h16 [(size_t)MAXN * HID];   // fp16 h1 then h2 (gather target)
__device__ __half g_A16 [(size_t)MAXN * HID];   // fp16 edge-head src projection
__device__ __half g_B16 [(size_t)MAXN * HID];   // fp16 edge-head dst projection
__device__ float  g_dinv[MAXN];
__device__ float  g_sum[HID];
__device__ float  g_sumsq[HID];
__device__ float  g_scale[HID];
__device__ float  g_shift[HID];
__device__ int    g_cnt[MAXN];
__device__ int    g_rowoff[MAXN + 1];
__device__ int    g_cursor[MAXN];
__device__ int    g_csr_src[MAXE];

// ---- packed f32x2 helpers (sm_103a FFMA2 path) ----
__device__ __forceinline__ uint64_t pack2(float lo, float hi)
{
    uint64_t r;
    asm("mov.b64 %0,{%1,%2};" : "=l"(r) : "f"(lo), "f"(hi));
    return r;
}
__device__ __forceinline__ void unpack2(uint64_t v, float& lo, float& hi)
{
    asm("mov.b64 {%0,%1},%2;" : "=f"(lo), "=f"(hi) : "l"(v));
}
__device__ __forceinline__ uint64_t fma2(uint64_t a, uint64_t b, uint64_t c)
{
    uint64_t d;
    asm("fma.rn.f32x2 %0,%1,%2,%3;" : "=l"(d) : "l"(a), "l"(b), "l"(c));
    return d;
}
__device__ __forceinline__ uint64_t add2(uint64_t a, uint64_t b)
{
    uint64_t d;
    asm("add.rn.f32x2 %0,%1,%2;" : "=l"(d) : "l"(a), "l"(b));
    return d;
}
// NOTE: redux.sync.add.f32 does NOT exist on sm_103 (integer only) -> butterfly.
__device__ __forceinline__ float warp_sum32(float p)
{
#pragma unroll
    for (int o = 16; o; o >>= 1) p += __shfl_xor_sync(FULLMASK, p, o);
    return p;
}

// ---------------------------------------------------------------------------
__global__ void zero_aux(int* __restrict__ cnt, float* __restrict__ sum,
                         float* __restrict__ sumsq, int n)
{
    int i = blockIdx.x * blockDim.x + threadIdx.x;
    if (i < n) cnt[i] = 0;
    if (i < HID) { sum[i] = 0.0f; sumsq[i] = 0.0f; }
}

__global__ void hist_dst(const int* __restrict__ dst, int* __restrict__ cnt, int E)
{
    int i = blockIdx.x * blockDim.x + threadIdx.x;
    if (i < E) atomicAdd(&cnt[dst[i]], 1);
}

// Single-block coalesced tiled exclusive scan. Emits rowoff, cursor, dinv.
__global__ __launch_bounds__(1024)
void scan_offsets(const int* __restrict__ cnt, int* __restrict__ rowoff,
                  int* __restrict__ cursor, float* __restrict__ dinv, int n)
{
    __shared__ int warp_sums[32];
    const int t = threadIdx.x;
    const int lane = t & 31;
    const int w = t >> 5;
    int carry = 0;

    for (int base = 0; base < n; base += 1024) {
        int i = base + t;
        int c = (i < n) ? cnt[i] : 0;
        int v = c;
#pragma unroll
        for (int o = 1; o < 32; o <<= 1) {
            int u = __shfl_up_sync(FULLMASK, v, o);
            if (lane >= o) v += u;
        }
        if (lane == 31) warp_sums[w] = v;
        __syncthreads();
        if (w == 0) {
            int sv = warp_sums[lane];
#pragma unroll
            for (int o = 1; o < 32; o <<= 1) {
                int u = __shfl_up_sync(FULLMASK, sv, o);
                if (lane >= o) sv += u;
            }
            warp_sums[lane] = sv;
        }
        __syncthreads();
        int excl = carry + (w ? warp_sums[w - 1] : 0) + v - c;
        if (i < n) {
            rowoff[i] = excl;
            cursor[i] = excl;
            dinv[i]   = rsqrtf((float)c + 1.0f);
        }
        int tile_total = warp_sums[31];
        __syncthreads();
        carry += tile_total;
    }
    if (t == 0) rowoff[n] = carry;
}

__global__ void fill_csr(const int* __restrict__ src, const int* __restrict__ dst,
                         int* __restrict__ cursor, int* __restrict__ csr_src, int E)
{
    int e = blockIdx.x * blockDim.x + threadIdx.x;
    if (e < E) {
        int d = dst[e];
        int pos = atomicAdd(&cursor[d], 1);
        csr_src[pos] = src[e];
    }
}

// ---------------------------------------------------------------------------
// tf32 tensor-core GEMM with 3xTF32 error compensation. Output fp16.
#define SMS 136
#define WSS 264

__device__ __forceinline__ uint32_t f2tf32(float x)
{
    uint32_t r;
    asm("cvt.rna.tf32.f32 %0, %1;" : "=r"(r) : "f"(x));
    return r;
}

__device__ __forceinline__ void mma_tf32(float c[4], const uint32_t a[4],
                                         uint32_t b0, uint32_t b1)
{
    asm volatile(
        "mma.sync.aligned.m16n8k8.row.col.f32.tf32.tf32.f32 "
        "{%0,%1,%2,%3},{%4,%5,%6,%7},{%8,%9},{%0,%1,%2,%3};"
        : "+f"(c[0]), "+f"(c[1]), "+f"(c[2]), "+f"(c[3])
        : "r"(a[0]), "r"(a[1]), "r"(a[2]), "r"(a[3]), "r"(b0), "r"(b1));
}

// C16[M,128] = f(A)[M,128] @ W[128,128]; f = optional scale/shift+relu.
__global__ __launch_bounds__(256)
void gemm_tf32(const float* __restrict__ A, const float* __restrict__ W,
               __half* __restrict__ C, int M,
               const float* __restrict__ pre_scale,
               const float* __restrict__ pre_shift)
{
    extern __shared__ float smem[];
    float* As = smem;              // [128][SMS]
    float* Ws = smem + 128 * SMS;  // [128][SMS]

    const int tid = threadIdx.x;
    const int blockRow = blockIdx.x * 128;
    const bool do_pre = (pre_scale != nullptr);

#pragma unroll
    for (int t = 0; t < 16; t++) {
        int idx = tid + t * 256;
        int row = idx >> 5;
        int c4  = (idx & 31) * 4;
        int gr  = blockRow + row;
        float4 av = (gr < M) ? *(const float4*)(A + (size_t)gr * HID + c4)
                             : make_float4(0.f, 0.f, 0.f, 0.f);
        if (do_pre) {
            float4 sc = *(const float4*)(pre_scale + c4);
            float4 sh = *(const float4*)(pre_shift + c4);
            av.x = fmaxf(av.x * sc.x + sh.x, 0.f);
            av.y = fmaxf(av.y * sc.y + sh.y, 0.f);
            av.z = fmaxf(av.z * sc.z + sh.z, 0.f);
            av.w = fmaxf(av.w * sc.w + sh.w, 0.f);
        }
        *(float4*)(As + row * SMS + c4) = av;
        *(float4*)(Ws + row * SMS + c4) = *(const float4*)(W + (size_t)row * HID + c4);
    }
    __syncthreads();

    const int lane = tid & 31;
    const int warp = tid >> 5;
    const int g    = lane >> 2;
    const int tig  = lane & 3;
    const int wm   = (warp >> 1) * 32;
    const int wn   = (warp & 1) * 64;

    float c[2][8][4];
#pragma unroll
    for (int mt = 0; mt < 2; mt++)
#pragma unroll
        for (int nt = 0; nt < 8; nt++)
#pragma unroll
            for (int i = 0; i < 4; i++) c[mt][nt][i] = 0.f;

#pragma unroll
    for (int kt = 0; kt < 16; kt++) {
        const int k0 = kt * 8;
        uint32_t ahi[2][4], alo[2][4];
#pragma unroll
        for (int mt = 0; mt < 2; mt++) {
            int rb = wm + mt * 16;
            float a0 = As[(rb + g)     * SMS + k0 + tig];
            float a1 = As[(rb + g + 8) * SMS + k0 + tig];
            float a2 = As[(rb + g)     * SMS + k0 + tig + 4];
            float a3 = As[(rb + g + 8) * SMS + k0 + tig + 4];
            ahi[mt][0] = f2tf32(a0); alo[mt][0] = f2tf32(a0 - __uint_as_float(ahi[mt][0]));
            ahi[mt][1] = f2tf32(a1); alo[mt][1] = f2tf32(a1 - __uint_as_float(ahi[mt][1]));
            ahi[mt][2] = f2tf32(a2); alo[mt][2] = f2tf32(a2 - __uint_as_float(ahi[mt][2]));
            ahi[mt][3] = f2tf32(a3); alo[mt][3] = f2tf32(a3 - __uint_as_float(ahi[mt][3]));
        }
#pragma unroll
        for (int nt = 0; nt < 8; nt++) {
            int col = wn + nt * 8 + g;
            float b0 = Ws[(k0 + tig)     * SMS + col];
            float b1 = Ws[(k0 + tig + 4) * SMS + col];
            uint32_t bh0 = f2tf32(b0), bh1 = f2tf32(b1);
            uint32_t bl0 = f2tf32(b0 - __uint_as_float(bh0));
            uint32_t bl1 = f2tf32(b1 - __uint_as_float(bh1));
#pragma unroll
            for (int mt = 0; mt < 2; mt++) {
                mma_tf32(c[mt][nt], ahi[mt], bh0, bh1);
                mma_tf32(c[mt][nt], ahi[mt], bl0, bl1);
                mma_tf32(c[mt][nt], alo[mt], bh0, bh1);
            }
        }
    }

#pragma unroll
    for (int mt = 0; mt < 2; mt++) {
#pragma unroll
        for (int nt = 0; nt < 8; nt++) {
            int row0 = blockRow + wm + mt * 16 + g;
            int col0 = wn + nt * 8 + 2 * tig;
            if (row0 < M)
                *(__half2*)(C + (size_t)row0 * HID + col0) =
                    __floats2half2_rn(c[mt][nt][0], c[mt][nt][1]);
            int row1 = row0 + 8;
            if (row1 < M)
                *(__half2*)(C + (size_t)row1 * HID + col0) =
                    __floats2half2_rn(c[mt][nt][2], c[mt][nt][3]);
        }
    }
}

// Fused projection GEMM: C0 = A @ W[0:128], C1 = A @ W[128:256], fp16 outputs.
__global__ __launch_bounds__(512)
void gemm_proj(const float* __restrict__ A, const float* __restrict__ W,
               __half* __restrict__ C0, __half* __restrict__ C1, int M)
{
    extern __shared__ float smem[];
    float* As = smem;              // [128][SMS]
    float* Ws = smem + 128 * SMS;  // [128][WSS]

    const int tid = threadIdx.x;
    const int blockRow = blockIdx.x * 128;

#pragma unroll
    for (int t = 0; t < 8; t++) {
        int idx = tid + t * 512;
        int row = idx >> 5;
        int c4  = (idx & 31) * 4;
        int gr  = blockRow + row;
        float4 av = (gr < M) ? *(const float4*)(A + (size_t)gr * HID + c4)
                             : make_float4(0.f, 0.f, 0.f, 0.f);
        *(float4*)(As + row * SMS + c4) = av;
    }
#pragma unroll
    for (int t = 0; t < 16; t++) {
        int idx = tid + t * 512;
        int r   = idx >> 5;
        int c4  = (idx & 31) * 4;
        int k    = r & 127;
        int half = r >> 7;
        *(float4*)(Ws + k * WSS + half * 128 + c4) =
            *(const float4*)(W + (size_t)r * HID + c4);
    }
    __syncthreads();

    const int lane = tid & 31;
    const int warp = tid >> 5;
    const int g    = lane >> 2;
    const int tig  = lane & 3;
    const int wm   = (warp >> 2) * 32;
    const int wn   = (warp & 3) * 64;

    float c[2][8][4];
#pragma unroll
    for (int mt = 0; mt < 2; mt++)
#pragma unroll
        for (int nt = 0; nt < 8; nt++)
#pragma unroll
            for (int i = 0; i < 4; i++) c[mt][nt][i] = 0.f;

#pragma unroll
    for (int kt = 0; kt < 16; kt++) {
        const int k0 = kt * 8;
        uint32_t ahi[2][4], alo[2][4];
#pragma unroll
        for (int mt = 0; mt < 2; mt++) {
            int rb = wm + mt * 16;
            float a0 = As[(rb + g)     * SMS + k0 + tig];
            float a1 = As[(rb + g + 8) * SMS + k0 + tig];
            float a2 = As[(rb + g)     * SMS + k0 + tig + 4];
            float a3 = As[(rb + g + 8) * SMS + k0 + tig + 4];
            ahi[mt][0] = f2tf32(a0); alo[mt][0] = f2tf32(a0 - __uint_as_float(ahi[mt][0]));
            ahi[mt][1] = f2tf32(a1); alo[mt][1] = f2tf32(a1 - __uint_as_float(ahi[mt][1]));
            ahi[mt][2] = f2tf32(a2); alo[mt][2] = f2tf32(a2 - __uint_as_float(ahi[mt][2]));
            ahi[mt][3] = f2tf32(a3); alo[mt][3] = f2tf32(a3 - __uint_as_float(ahi[mt][3]));
        }
#pragma unroll
        for (int nt = 0; nt < 8; nt++) {
            int col = wn + nt * 8 + g;
            float b0 = Ws[(k0 + tig)     * WSS + col];
            float b1 = Ws[(k0 + tig + 4) * WSS + col];
            uint32_t bh0 = f2tf32(b0), bh1 = f2tf32(b1);
            uint32_t bl0 = f2tf32(b0 - __uint_as_float(bh0));
            uint32_t bl1 = f2tf32(b1 - __uint_as_float(bh1));
#pragma unroll
            for (int mt = 0; mt < 2; mt++) {
                mma_tf32(c[mt][nt], ahi[mt], bh0, bh1);
                mma_tf32(c[mt][nt], ahi[mt], bl0, bl1);
                mma_tf32(c[mt][nt], alo[mt], bh0, bh1);
            }
        }
    }

    __half* Cb = (wn < 128) ? C0 : C1;
    const int cbase = (wn < 128) ? wn : wn - 128;
#pragma unroll
    for (int mt = 0; mt < 2; mt++) {
#pragma unroll
        for (int nt = 0; nt < 8; nt++) {
            int row0 = blockRow + wm + mt * 16 + g;
            int col0 = cbase + nt * 8 + 2 * tig;
            if (row0 < M)
                *(__half2*)(Cb + (size_t)row0 * HID + col0) =
                    __floats2half2_rn(c[mt][nt][0], c[mt][nt][1]);
            int row1 = row0 + 8;
            if (row1 < M)
                *(__half2*)(Cb + (size_t)row1 * HID + col0) =
                    __floats2half2_rn(c[mt][nt][2], c[mt][nt][3]);
        }
    }
}

// ---------------------------------------------------------------------------
// agg[n,:] = sum_{e: dst=n} h[src_e,:]*dinv[src]*dinv[n] + h[n,:]*dinv[n]^2 + b
// Half-warp per gathered row: lane loads uint4 (8 fp16 ch), warp processes
// 2 edges per round. fp32 (f32x2) accumulation; halves merged via shfl_xor.
__global__ __launch_bounds__(256)
void gcn_aggregate(const __half* __restrict__ h, float* __restrict__ agg,
                   const int* __restrict__ rowoff, const int* __restrict__ csr_src,
                   const float* __restrict__ dinv, const float* __restrict__ bias,
                   int Nn)
{
    const int lane = threadIdx.x & 31;
    const int n = (blockIdx.x * blockDim.x + threadIdx.x) >> 5;
    if (n >= Nn) return;
    const int hw = lane >> 4;          // half-warp id
    const int c8 = (lane & 15) * 8;    // 8 channels per lane

    const float din = dinv[n];
    uint64_t a0, a1, a2, a3;
    if (hw == 0) {
        float wsl = din * din;
        uint4 hv = *(const uint4*)(h + (size_t)n * HID + c8);
        float2 t0 = __half22float2(*(const __half2*)&hv.x);
        float2 t1 = __half22float2(*(const __half2*)&hv.y);
        float2 t2 = __half22float2(*(const __half2*)&hv.z);
        float2 t3 = __half22float2(*(const __half2*)&hv.w);
        float4 bb0 = *(const float4*)(bias + c8);
        float4 bb1 = *(const float4*)(bias + c8 + 4);
        a0 = pack2(t0.x * wsl + bb0.x, t0.y * wsl + bb0.y);
        a1 = pack2(t1.x * wsl + bb0.z, t1.y * wsl + bb0.w);
        a2 = pack2(t2.x * wsl + bb1.x, t2.y * wsl + bb1.y);
        a3 = pack2(t3.x * wsl + bb1.z, t3.y * wsl + bb1.w);
    } else {
        a0 = a1 = a2 = a3 = 0ull;
    }

    const int beg = rowoff[n], end = rowoff[n + 1];
    for (int base = beg; base < end; base += 32) {
        int m = min(32, end - base);
        int s = 0;
        float ww = 0.f;
        if (lane < m) {
            s = __ldg(&csr_src[base + lane]);
            ww = dinv[s] * din;
        }
        int j = 0;
#pragma unroll 4
        for (; j + 2 <= m; j += 2) {
            int   sj = __shfl_sync(FULLMASK, s,  j + hw);
            float wj = __shfl_sync(FULLMASK, ww, j + hw);
            uint4 rv = *(const uint4*)(h + (size_t)sj * HID + c8);
            uint64_t wj2 = pack2(wj, wj);
            float2 r0 = __half22float2(*(const __half2*)&rv.x);
            float2 r1 = __half22float2(*(const __half2*)&rv.y);
            float2 r2 = __half22float2(*(const __half2*)&rv.z);
            float2 r3 = __half22float2(*(const __half2*)&rv.w);
            a0 = fma2(pack2(r0.x, r0.y), wj2, a0);
            a1 = fma2(pack2(r1.x, r1.y), wj2, a1);
            a2 = fma2(pack2(r2.x, r2.y), wj2, a2);
            a3 = fma2(pack2(r3.x, r3.y), wj2, a3);
        }
        if (j < m) {   // odd tail: half-warp 0 handles the last edge
            int   sj = __shfl_sync(FULLMASK, s,  j);
            float wj = __shfl_sync(FULLMASK, ww, j);
            if (hw == 0) {
                uint4 rv = *(const uint4*)(h + (size_t)sj * HID + c8);
                uint64_t wj2 = pack2(wj, wj);
                float2 r0 = __half22float2(*(const __half2*)&rv.x);
                float2 r1 = __half22float2(*(const __half2*)&rv.y);
                float2 r2 = __half22float2(*(const __half2*)&rv.z);
                float2 r3 = __half22float2(*(const __half2*)&rv.w);
                a0 = fma2(pack2(r0.x, r0.y), wj2, a0);
                a1 = fma2(pack2(r1.x, r1.y), wj2, a1);
                a2 = fma2(pack2(r2.x, r2.y), wj2, a2);
                a3 = fma2(pack2(r3.x, r3.y), wj2, a3);
            }
        }
    }

    // merge the two half-warps (same channels, disjoint edge subsets)
    a0 = add2(a0, __shfl_xor_sync(FULLMASK, a0, 16));
    a1 = add2(a1, __shfl_xor_sync(FULLMASK, a1, 16));
    a2 = add2(a2, __shfl_xor_sync(FULLMASK, a2, 16));
    a3 = add2(a3, __shfl_xor_sync(FULLMASK, a3, 16));

    if (hw == 0) {
        float f0, f1, f2, f3, f4, f5, f6, f7;
        unpack2(a0, f0, f1);
        unpack2(a1, f2, f3);
        unpack2(a2, f4, f5);
        unpack2(a3, f6, f7);
        *(float4*)(agg + (size_t)n * HID + c8)     = make_float4(f0, f1, f2, f3);
        *(float4*)(agg + (size_t)n * HID + c8 + 4) = make_float4(f4, f5, f6, f7);
    }
}

// ---------------------------------------------------------------------------
__global__ __launch_bounds__(256)
void bn_stats(const float* __restrict__ z, float* __restrict__ sum,
              float* __restrict__ sumsq, int Nn)
{
    __shared__ float sh[8][128];
    const int w  = threadIdx.x >> 5;
    const int c4 = (threadIdx.x & 31) * 4;

    float4 s = make_float4(0.f, 0.f, 0.f, 0.f);
    float4 q = make_float4(0.f, 0.f, 0.f, 0.f);
    for (int r = blockIdx.x * 8 + w; r < Nn; r += gridDim.x * 8) {
        float4 v = *(const float4*)(z + (size_t)r * HID + c4);
        s.x += v.x; s.y += v.y; s.z += v.z; s.w += v.w;
        q.x = fmaf(v.x, v.x, q.x);
        q.y = fmaf(v.y, v.y, q.y);
        q.z = fmaf(v.z, v.z, q.z);
        q.w = fmaf(v.w, v.w, q.w);
    }
    *(float4*)&sh[w][c4] = s;
    __syncthreads();
    if (threadIdx.x < 128) {
        int c = threadIdx.x;
        float t = sh[0][c] + sh[1][c] + sh[2][c] + sh[3][c]
                + sh[4][c] + sh[5][c] + sh[6][c] + sh[7][c];
        atomicAdd(&sum[c], t);
    }
    __syncthreads();
    *(float4*)&sh[w][c4] = q;
    __syncthreads();
    if (threadIdx.x < 128) {
        int c = threadIdx.x;
        float t = sh[0][c] + sh[1][c] + sh[2][c] + sh[3][c]
                + sh[4][c] + sh[5][c] + sh[6][c] + sh[7][c];
        atomicAdd(&sumsq[c], t);
    }
}

__global__ void bn_final(const float* __restrict__ sum, const float* __restrict__ sumsq,
                         const float* __restrict__ gamma, const float* __restrict__ beta,
                         float* __restrict__ scale, float* __restrict__ shift, int Nn)
{
    int i = threadIdx.x;
    if (i < HID) {
        float invN = 1.0f / (float)Nn;
        float mean = sum[i] * invN;
        float var  = sumsq[i] * invN - mean * mean;
        float sc   = gamma[i] * rsqrtf(var + 1e-5f);
        scale[i] = sc;
        shift[i] = beta[i] - mean * sc;
    }
}

// ---------------------------------------------------------------------------
// out[e] = relu(A[src] + B[dst] + edge_attr[e]@We + bm1) . Wm2 + bm2
// fp16 A/B gathers; 4 independent fma2 chains; shfl_xor butterfly reduction.
__global__ __launch_bounds__(256)
void edge_mlp(const __half* __restrict__ A, const __half* __restrict__ B,
              const int* __restrict__ src, const int* __restrict__ dst,
              const float* __restrict__ ea, const float* __restrict__ We,  // [16,128]
              const float* __restrict__ bm1, const float* __restrict__ Wm2,
              const float* __restrict__ bm2, float* __restrict__ out, int E)
{
    int lane = threadIdx.x & 31;
    int warp = (blockIdx.x * blockDim.x + threadIdx.x) >> 5;
    int nw   = (gridDim.x * blockDim.x) >> 5;
    int c4   = lane * 4;

    uint64_t wp0[16], wp1[16];
#pragma unroll
    for (int k = 0; k < 16; k++) {
        ulonglong2 wv = *(const ulonglong2*)(We + (size_t)k * HID + c4);
        wp0[k] = wv.x;
        wp1[k] = wv.y;
    }
    float4 bv = *(const float4*)(bm1 + c4);
    float4 w2 = *(const float4*)(Wm2 + c4);
    const float bm2v = __ldg(bm2);

    for (int base = warp * 32; base < E; base += nw * 32) {
        int m = min(32, E - base);
        int s = 0, d = 0;
        if (lane < m) {
            s = __ldg(&src[base + lane]);
            d = __ldg(&dst[base + lane]);
        }
        float res = 0.f;
        for (int j = 0; j < m; j++) {
            int sj = __shfl_sync(FULLMASK, s, j);
            int dj = __shfl_sync(FULLMASK, d, j);
            uint2 av2 = *(const uint2*)(A + (size_t)sj * HID + c4);
            uint2 bv2 = *(const uint2*)(B + (size_t)dj * HID + c4);
            float2 a0 = __half22float2(*(const __half2*)&av2.x);
            float2 a1 = __half22float2(*(const __half2*)&av2.y);
            float2 b0 = __half22float2(*(const __half2*)&bv2.x);
            float2 b1 = __half22float2(*(const __half2*)&bv2.y);
            // two chains per channel pair -> 4 independent 8-deep chains
            uint64_t acc0 = pack2(a0.x + b0.x + bv.x, a0.y + b0.y + bv.y);
            uint64_t acc1 = pack2(a1.x + b1.x + bv.z, a1.y + b1.y + bv.w);
            uint64_t accB0 = 0ull, accB1 = 0ull;

            const float4* eap = (const float4*)(ea + (size_t)(base + j) * 16);
            float4 e4a = __ldg(&eap[0]);   // uniform across warp -> broadcast
            float4 e4b = __ldg(&eap[1]);
            float4 e4c = __ldg(&eap[2]);
            float4 e4d = __ldg(&eap[3]);
            uint64_t ex;
            // k = 0..3 (chain A)
            ex = pack2(e4a.x, e4a.x); acc0  = fma2(wp0[0],  ex, acc0);  acc1  = fma2(wp1[0],  ex, acc1);
            ex = pack2(e4a.y, e4a.y); acc0  = fma2(wp0[1],  ex, acc0);  acc1  = fma2(wp1[1],  ex, acc1);
            ex = pack2(e4a.z, e4a.z); acc0  = fma2(wp0[2],  ex, acc0);  acc1  = fma2(wp1[2],  ex, acc1);
            ex = pack2(e4a.w, e4a.w); acc0  = fma2(wp0[3],  ex, acc0);  acc1  = fma2(wp1[3],  ex, acc1);
            // k = 4..7 (chain B)
            ex = pack2(e4b.x, e4b.x); accB0 = fma2(wp0[4],  ex, accB0); accB1 = fma2(wp1[4],  ex, accB1);
            ex = pack2(e4b.y, e4b.y); accB0 = fma2(wp0[5],  ex, accB0); accB1 = fma2(wp1[5],  ex, accB1);
            ex = pack2(e4b.z, e4b.z); accB0 = fma2(wp0[6],  ex, accB0); accB1 = fma2(wp1[6],  ex, accB1);
            ex = pack2(e4b.w, e4b.w); accB0 = fma2(wp0[7],  ex, accB0); accB1 = fma2(wp1[7],  ex, accB1);
            // k = 8..11 (chain A)
            ex = pack2(e4c.x, e4c.x); acc0  = fma2(wp0[8],  ex, acc0);  acc1  = fma2(wp1[8],  ex, acc1);
            ex = pack2(e4c.y, e4c.y); acc0  = fma2(wp0[9],  ex, acc0);  acc1  = fma2(wp1[9],  ex, acc1);
            ex = pack2(e4c.z, e4c.z); acc0  = fma2(wp0[10], ex, acc0);  acc1  = fma2(wp1[10], ex, acc1);
            ex = pack2(e4c.w, e4c.w); acc0  = fma2(wp0[11], ex, acc0);  acc1  = fma2(wp1[11], ex, acc1);
            // k = 12..15 (chain B)
            ex = pack2(e4d.x, e4d.x); accB0 = fma2(wp0[12], ex, accB0); accB1 = fma2(wp1[12], ex, accB1);
            ex = pack2(e4d.y, e4d.y); accB0 = fma2(wp0[13], ex, accB0); accB1 = fma2(wp1[13], ex, accB1);
            ex = pack2(e4d.z, e4d.z); accB0 = fma2(wp0[14], ex, accB0); accB1 = fma2(wp1[14], ex, accB1);
            ex = pack2(e4d.w, e4d.w); accB0 = fma2(wp0[15], ex, accB0); accB1 = fma2(wp1[15], ex, accB1);

            acc0 = add2(acc0, accB0);
            acc1 = add2(acc1, accB1);

            float f0, f1, f2, f3;
            unpack2(acc0, f0, f1);
            unpack2(acc1, f2, f3);
            f0 = fmaxf(f0, 0.f);
            f1 = fmaxf(f1, 0.f);
            f2 = fmaxf(f2, 0.f);
            f3 = fmaxf(f3, 0.f);

            float p = f0 * w2.x + f1 * w2.y + f2 * w2.z + f3 * w2.w;
            float tot = warp_sum32(p);
            if (lane == j) res = tot + bm2v;
        }
        if (lane < m) out[base + lane] = res;   // coalesced 128B store
    }
}

// ---------------------------------------------------------------------------
extern "C" void kernel_launch(void* const* d_in, const int* in_sizes, int n_in,
                              void* d_out, int out_size)
{
    const float* x     = (const float*)d_in[0];
    const int*   ei    = (const int*)  d_in[1];
    const float* ea    = (const float*)d_in[2];
    const float* W1    = (const float*)d_in[3];
    const float* b1    = (const float*)d_in[4];
    const float* gamma = (const float*)d_in[5];
    const float* beta  = (const float*)d_in[6];
    const float* W2    = (const float*)d_in[7];
    const float* b2    = (const float*)d_in[8];
    const float* Wm1   = (const float*)d_in[9];
    const float* bm1   = (const float*)d_in[10];
    const float* Wm2   = (const float*)d_in[11];
    const float* bm2   = (const float*)d_in[12];
    float* out = (float*)d_out;

    const int Nn = in_sizes[0] / HID;
    const int E  = in_sizes[1] / 2;
    const int* src = ei;
    const int* dst = ei + E;

    float *buf0, *dinv, *sum, *sumsq, *scale, *shift;
    __half *h16, *A16, *B16;
    int *cnt, *rowoff, *cursor, *csr_src;
    cudaGetSymbolAddress((void**)&buf0,    g_buf0);
    cudaGetSymbolAddress((void**)&h16,     g_h16);
    cudaGetSymbolAddress((void**)&A16,     g_A16);
    cudaGetSymbolAddress((void**)&B16,     g_B16);
    cudaGetSymbolAddress((void**)&dinv,    g_dinv);
    cudaGetSymbolAddress((void**)&sum,     g_sum);
    cudaGetSymbolAddress((void**)&sumsq,   g_sumsq);
    cudaGetSymbolAddress((void**)&scale,   g_scale);
    cudaGetSymbolAddress((void**)&shift,   g_shift);
    cudaGetSymbolAddress((void**)&cnt,     g_cnt);
    cudaGetSymbolAddress((void**)&rowoff,  g_rowoff);
    cudaGetSymbolAddress((void**)&cursor,  g_cursor);
    cudaGetSymbolAddress((void**)&csr_src, g_csr_src);

    const int SMEM  = 2 * 128 * SMS * (int)sizeof(float);
    const int SMEMP = 128 * (SMS + WSS) * (int)sizeof(float);
    cudaFuncSetAttribute(gemm_tf32, cudaFuncAttributeMaxDynamicSharedMemorySize, SMEM);
    cudaFuncSetAttribute(gemm_proj, cudaFuncAttributeMaxDynamicSharedMemorySize, SMEMP);

    const int gN    = (Nn + 255) / 256;
    const int gE    = (E + 255) / 256;
    const int gGemm = (Nn + 127) / 128;
    const int gAgg  = (Nn * 32 + 255) / 256;

    // CSR build (by dst) + degrees
    zero_aux<<<gN, 256>>>(cnt, sum, sumsq, Nn);
    hist_dst<<<gE, 256>>>(dst, cnt, E);
    scan_offsets<<<1, 1024>>>(cnt, rowoff, cursor, dinv, Nn);
    fill_csr<<<gE, 256>>>(src, dst, cursor, csr_src, E);

    // conv1: h1 = x @ W1 (fp16) ; agg1 = CSR gather + self-loop + b1 (fp32)
    gemm_tf32<<<gGemm, 256, SMEM>>>(x, W1, h16, Nn, nullptr, nullptr);
    gcn_aggregate<<<gAgg, 256>>>(h16, buf0, rowoff, csr_src, dinv, b1, Nn);

    // batchnorm stats (apply fused into next GEMM's A staging)
    bn_stats<<<512, 256>>>(buf0, sum, sumsq, Nn);
    bn_final<<<1, 128>>>(sum, sumsq, gamma, beta, scale, shift, Nn);

    // conv2: h2 = relu(bn(agg1)) @ W2 (fp16) ; agg2 (fp32, reuse buf0)
    gemm_tf32<<<gGemm, 256, SMEM>>>(buf0, W2, h16, Nn, scale, shift);
    gcn_aggregate<<<gAgg, 256>>>(h16, buf0, rowoff, csr_src, dinv, b2, Nn);

    // fused per-node projections: A16 = z2@Wm1[0:128], B16 = z2@Wm1[128:256]
    gemm_proj<<<gGemm, 512, SMEMP>>>(buf0, Wm1, A16, B16, Nn);

    // fused edge head
    edge_mlp<<<2048, 256>>>(A16, B16, src, dst, ea, Wm1 + 256 * HID,
                            bm1, Wm2, bm2, out, E);
}

// round 8
// speedup vs baseline: 1.0271x; 1.0271x over previous
#include <cuda_runtime.h>
#include <cuda_fp16.h>
#include <cstdint>

#define MAXN 50000
#define MAXE 800000
#define HID 128
#define FULLMASK 0xffffffffu

// ---- static scratch (no allocations allowed) ----
__device__ float  g_buf0[(size_t)MAXN * HID];   // fp32 aggregate outputs
__device__ __half g_h16 [(size_t)MAXN * HID];   // fp16 h1 then h2 (gather target)
__device__ __half g_A16 [(size_t)MAXN * HID];   // fp16 edge-head src projection
__device__ __half g_B16 [(size_t)MAXN * HID];   // fp16 edge-head dst projection
__device__ __half g_q16 [(size_t)MAXE * HID];   // fp16 per-edge ea@We + bm1
__device__ float  g_dinv[MAXN];
__device__ float  g_sum[HID];
__device__ float  g_sumsq[HID];
__device__ float  g_scale[HID];
__device__ float  g_shift[HID];
__device__ int    g_cnt[MAXN];
__device__ int    g_rowoff[MAXN + 1];
__device__ int    g_cursor[MAXN];
__device__ int    g_csr_src[MAXE];

// ---- packed f32x2 helpers (sm_103a FFMA2 path) ----
__device__ __forceinline__ uint64_t pack2(float lo, float hi)
{
    uint64_t r;
    asm("mov.b64 %0,{%1,%2};" : "=l"(r) : "f"(lo), "f"(hi));
    return r;
}
__device__ __forceinline__ void unpack2(uint64_t v, float& lo, float& hi)
{
    asm("mov.b64 {%0,%1},%2;" : "=f"(lo), "=f"(hi) : "l"(v));
}
__device__ __forceinline__ uint64_t fma2(uint64_t a, uint64_t b, uint64_t c)
{
    uint64_t d;
    asm("fma.rn.f32x2 %0,%1,%2,%3;" : "=l"(d) : "l"(a), "l"(b), "l"(c));
    return d;
}
// NOTE: redux.sync.add.f32 does NOT exist on sm_103 -> butterfly.
__device__ __forceinline__ float warp_sum32(float p)
{
#pragma unroll
    for (int o = 16; o; o >>= 1) p += __shfl_xor_sync(FULLMASK, p, o);
    return p;
}

// ---------------------------------------------------------------------------
__global__ void zero_aux(int* __restrict__ cnt, float* __restrict__ sum,
                         float* __restrict__ sumsq, int n)
{
    int i = blockIdx.x * blockDim.x + threadIdx.x;
    if (i < n) cnt[i] = 0;
    if (i < HID) { sum[i] = 0.0f; sumsq[i] = 0.0f; }
}

__global__ void hist_dst(const int* __restrict__ dst, int* __restrict__ cnt, int E)
{
    int i = blockIdx.x * blockDim.x + threadIdx.x;
    if (i < E) atomicAdd(&cnt[dst[i]], 1);
}

// Single-block coalesced tiled exclusive scan. Emits rowoff, cursor, dinv.
__global__ __launch_bounds__(1024)
void scan_offsets(const int* __restrict__ cnt, int* __restrict__ rowoff,
                  int* __restrict__ cursor, float* __restrict__ dinv, int n)
{
    __shared__ int warp_sums[32];
    const int t = threadIdx.x;
    const int lane = t & 31;
    const int w = t >> 5;
    int carry = 0;

    for (int base = 0; base < n; base += 1024) {
        int i = base + t;
        int c = (i < n) ? cnt[i] : 0;
        int v = c;
#pragma unroll
        for (int o = 1; o < 32; o <<= 1) {
            int u = __shfl_up_sync(FULLMASK, v, o);
            if (lane >= o) v += u;
        }
        if (lane == 31) warp_sums[w] = v;
        __syncthreads();
        if (w == 0) {
            int sv = warp_sums[lane];
#pragma unroll
            for (int o = 1; o < 32; o <<= 1) {
                int u = __shfl_up_sync(FULLMASK, sv, o);
                if (lane >= o) sv += u;
            }
            warp_sums[lane] = sv;
        }
        __syncthreads();
        int excl = carry + (w ? warp_sums[w - 1] : 0) + v - c;
        if (i < n) {
            rowoff[i] = excl;
            cursor[i] = excl;
            dinv[i]   = rsqrtf((float)c + 1.0f);
        }
        int tile_total = warp_sums[31];
        __syncthreads();
        carry += tile_total;
    }
    if (t == 0) rowoff[n] = carry;
}

__global__ void fill_csr(const int* __restrict__ src, const int* __restrict__ dst,
                         int* __restrict__ cursor, int* __restrict__ csr_src, int E)
{
    int e = blockIdx.x * blockDim.x + threadIdx.x;
    if (e < E) {
        int d = dst[e];
        int pos = atomicAdd(&cursor[d], 1);
        csr_src[pos] = src[e];
    }
}

// ---------------------------------------------------------------------------
// tf32 tensor-core GEMM with 3xTF32 error compensation. Output fp16.
#define SMS 136
#define WSS 264

__device__ __forceinline__ uint32_t f2tf32(float x)
{
    uint32_t r;
    asm("cvt.rna.tf32.f32 %0, %1;" : "=r"(r) : "f"(x));
    return r;
}

__device__ __forceinline__ void mma_tf32(float c[4], const uint32_t a[4],
                                         uint32_t b0, uint32_t b1)
{
    asm volatile(
        "mma.sync.aligned.m16n8k8.row.col.f32.tf32.tf32.f32 "
        "{%0,%1,%2,%3},{%4,%5,%6,%7},{%8,%9},{%0,%1,%2,%3};"
        : "+f"(c[0]), "+f"(c[1]), "+f"(c[2]), "+f"(c[3])
        : "r"(a[0]), "r"(a[1]), "r"(a[2]), "r"(a[3]), "r"(b0), "r"(b1));
}

// C16[M,128] = f(A)[M,128] @ W[128,128]; f = optional scale/shift+relu.
__global__ __launch_bounds__(256)
void gemm_tf32(const float* __restrict__ A, const float* __restrict__ W,
               __half* __restrict__ C, int M,
               const float* __restrict__ pre_scale,
               const float* __restrict__ pre_shift)
{
    extern __shared__ float smem[];
    float* As = smem;              // [128][SMS]
    float* Ws = smem + 128 * SMS;  // [128][SMS]

    const int tid = threadIdx.x;
    const int blockRow = blockIdx.x * 128;
    const bool do_pre = (pre_scale != nullptr);

#pragma unroll
    for (int t = 0; t < 16; t++) {
        int idx = tid + t * 256;
        int row = idx >> 5;
        int c4  = (idx & 31) * 4;
        int gr  = blockRow + row;
        float4 av = (gr < M) ? *(const float4*)(A + (size_t)gr * HID + c4)
                             : make_float4(0.f, 0.f, 0.f, 0.f);
        if (do_pre) {
            float4 sc = *(const float4*)(pre_scale + c4);
            float4 sh = *(const float4*)(pre_shift + c4);
            av.x = fmaxf(av.x * sc.x + sh.x, 0.f);
            av.y = fmaxf(av.y * sc.y + sh.y, 0.f);
            av.z = fmaxf(av.z * sc.z + sh.z, 0.f);
            av.w = fmaxf(av.w * sc.w + sh.w, 0.f);
        }
        *(float4*)(As + row * SMS + c4) = av;
        *(float4*)(Ws + row * SMS + c4) = *(const float4*)(W + (size_t)row * HID + c4);
    }
    __syncthreads();

    const int lane = tid & 31;
    const int warp = tid >> 5;
    const int g    = lane >> 2;
    const int tig  = lane & 3;
    const int wm   = (warp >> 1) * 32;
    const int wn   = (warp & 1) * 64;

    float c[2][8][4];
#pragma unroll
    for (int mt = 0; mt < 2; mt++)
#pragma unroll
        for (int nt = 0; nt < 8; nt++)
#pragma unroll
            for (int i = 0; i < 4; i++) c[mt][nt][i] = 0.f;

#pragma unroll
    for (int kt = 0; kt < 16; kt++) {
        const int k0 = kt * 8;
        uint32_t ahi[2][4], alo[2][4];
#pragma unroll
        for (int mt = 0; mt < 2; mt++) {
            int rb = wm + mt * 16;
            float a0 = As[(rb + g)     * SMS + k0 + tig];
            float a1 = As[(rb + g + 8) * SMS + k0 + tig];
            float a2 = As[(rb + g)     * SMS + k0 + tig + 4];
            float a3 = As[(rb + g + 8) * SMS + k0 + tig + 4];
            ahi[mt][0] = f2tf32(a0); alo[mt][0] = f2tf32(a0 - __uint_as_float(ahi[mt][0]));
            ahi[mt][1] = f2tf32(a1); alo[mt][1] = f2tf32(a1 - __uint_as_float(ahi[mt][1]));
            ahi[mt][2] = f2tf32(a2); alo[mt][2] = f2tf32(a2 - __uint_as_float(ahi[mt][2]));
            ahi[mt][3] = f2tf32(a3); alo[mt][3] = f2tf32(a3 - __uint_as_float(ahi[mt][3]));
        }
#pragma unroll
        for (int nt = 0; nt < 8; nt++) {
            int col = wn + nt * 8 + g;
            float b0 = Ws[(k0 + tig)     * SMS + col];
            float b1 = Ws[(k0 + tig + 4) * SMS + col];
            uint32_t bh0 = f2tf32(b0), bh1 = f2tf32(b1);
            uint32_t bl0 = f2tf32(b0 - __uint_as_float(bh0));
            uint32_t bl1 = f2tf32(b1 - __uint_as_float(bh1));
#pragma unroll
            for (int mt = 0; mt < 2; mt++) {
                mma_tf32(c[mt][nt], ahi[mt], bh0, bh1);
                mma_tf32(c[mt][nt], ahi[mt], bl0, bl1);
                mma_tf32(c[mt][nt], alo[mt], bh0, bh1);
            }
        }
    }

#pragma unroll
    for (int mt = 0; mt < 2; mt++) {
#pragma unroll
        for (int nt = 0; nt < 8; nt++) {
            int row0 = blockRow + wm + mt * 16 + g;
            int col0 = wn + nt * 8 + 2 * tig;
            if (row0 < M)
                *(__half2*)(C + (size_t)row0 * HID + col0) =
                    __floats2half2_rn(c[mt][nt][0], c[mt][nt][1]);
            int row1 = row0 + 8;
            if (row1 < M)
                *(__half2*)(C + (size_t)row1 * HID + col0) =
                    __floats2half2_rn(c[mt][nt][2], c[mt][nt][3]);
        }
    }
}

// Fused projection GEMM: C0 = A @ W[0:128], C1 = A @ W[128:256], fp16 outputs.
__global__ __launch_bounds__(512)
void gemm_proj(const float* __restrict__ A, const float* __restrict__ W,
               __half* __restrict__ C0, __half* __restrict__ C1, int M)
{
    extern __shared__ float smem[];
    float* As = smem;              // [128][SMS]
    float* Ws = smem + 128 * SMS;  // [128][WSS]

    const int tid = threadIdx.x;
    const int blockRow = blockIdx.x * 128;

#pragma unroll
    for (int t = 0; t < 8; t++) {
        int idx = tid + t * 512;
        int row = idx >> 5;
        int c4  = (idx & 31) * 4;
        int gr  = blockRow + row;
        float4 av = (gr < M) ? *(const float4*)(A + (size_t)gr * HID + c4)
                             : make_float4(0.f, 0.f, 0.f, 0.f);
        *(float4*)(As + row * SMS + c4) = av;
    }
#pragma unroll
    for (int t = 0; t < 16; t++) {
        int idx = tid + t * 512;
        int r   = idx >> 5;
        int c4  = (idx & 31) * 4;
        int k    = r & 127;
        int half = r >> 7;
        *(float4*)(Ws + k * WSS + half * 128 + c4) =
            *(const float4*)(W + (size_t)r * HID + c4);
    }
    __syncthreads();

    const int lane = tid & 31;
    const int warp = tid >> 5;
    const int g    = lane >> 2;
    const int tig  = lane & 3;
    const int wm   = (warp >> 2) * 32;
    const int wn   = (warp & 3) * 64;

    float c[2][8][4];
#pragma unroll
    for (int mt = 0; mt < 2; mt++)
#pragma unroll
        for (int nt = 0; nt < 8; nt++)
#pragma unroll
            for (int i = 0; i < 4; i++) c[mt][nt][i] = 0.f;

#pragma unroll
    for (int kt = 0; kt < 16; kt++) {
        const int k0 = kt * 8;
        uint32_t ahi[2][4], alo[2][4];
#pragma unroll
        for (int mt = 0; mt < 2; mt++) {
            int rb = wm + mt * 16;
            float a0 = As[(rb + g)     * SMS + k0 + tig];
            float a1 = As[(rb + g + 8) * SMS + k0 + tig];
            float a2 = As[(rb + g)     * SMS + k0 + tig + 4];
            float a3 = As[(rb + g + 8) * SMS + k0 + tig + 4];
            ahi[mt][0] = f2tf32(a0); alo[mt][0] = f2tf32(a0 - __uint_as_float(ahi[mt][0]));
            ahi[mt][1] = f2tf32(a1); alo[mt][1] = f2tf32(a1 - __uint_as_float(ahi[mt][1]));
            ahi[mt][2] = f2tf32(a2); alo[mt][2] = f2tf32(a2 - __uint_as_float(ahi[mt][2]));
            ahi[mt][3] = f2tf32(a3); alo[mt][3] = f2tf32(a3 - __uint_as_float(ahi[mt][3]));
        }
#pragma unroll
        for (int nt = 0; nt < 8; nt++) {
            int col = wn + nt * 8 + g;
            float b0 = Ws[(k0 + tig)     * WSS + col];
            float b1 = Ws[(k0 + tig + 4) * WSS + col];
            uint32_t bh0 = f2tf32(b0), bh1 = f2tf32(b1);
            uint32_t bl0 = f2tf32(b0 - __uint_as_float(bh0));
            uint32_t bl1 = f2tf32(b1 - __uint_as_float(bh1));
#pragma unroll
            for (int mt = 0; mt < 2; mt++) {
                mma_tf32(c[mt][nt], ahi[mt], bh0, bh1);
                mma_tf32(c[mt][nt], ahi[mt], bl0, bl1);
                mma_tf32(c[mt][nt], alo[mt], bh0, bh1);
            }
        }
    }

    __half* Cb = (wn < 128) ? C0 : C1;
    const int cbase = (wn < 128) ? wn : wn - 128;
#pragma unroll
    for (int mt = 0; mt < 2; mt++) {
#pragma unroll
        for (int nt = 0; nt < 8; nt++) {
            int row0 = blockRow + wm + mt * 16 + g;
            int col0 = cbase + nt * 8 + 2 * tig;
            if (row0 < M)
                *(__half2*)(Cb + (size_t)row0 * HID + col0) =
                    __floats2half2_rn(c[mt][nt][0], c[mt][nt][1]);
            int row1 = row0 + 8;
            if (row1 < M)
                *(__half2*)(Cb + (size_t)row1 * HID + col0) =
                    __floats2half2_rn(c[mt][nt][2], c[mt][nt][3]);
        }
    }
}

// ---------------------------------------------------------------------------
// q[E,128] = ea[E,16] @ We[16,128] + bm1, fp16 output. 1xTF32 (error ~5e-5:
// per-term magnitude ~0.06, 16 terms -> negligible vs fp16 storage error).
#define QSS 20    // ea smem stride (floats)
#define QWS 132   // We smem stride (floats)

__global__ __launch_bounds__(256)
void gemm_q(const float* __restrict__ ea, const float* __restrict__ We,
            const float* __restrict__ bm1, __half* __restrict__ q, int E)
{
    __shared__ float eas[128 * QSS];
    __shared__ float ws [16 * QWS];
    __shared__ float bs [128];

    const int tid = threadIdx.x;
    const int blockRow = blockIdx.x * 128;

    // stage ea tile [128,16] (512 float4 loads)
#pragma unroll
    for (int t = 0; t < 2; t++) {
        int idx = tid + t * 256;         // 0..511
        int row = idx >> 2;
        int c4  = (idx & 3) * 4;
        int gr  = blockRow + row;
        float4 v = (gr < E) ? *(const float4*)(ea + (size_t)gr * 16 + c4)
                            : make_float4(0.f, 0.f, 0.f, 0.f);
        *(float4*)(eas + row * QSS + c4) = v;
    }
    // stage We [16,128] (512 float4 loads)
#pragma unroll
    for (int t = 0; t < 2; t++) {
        int idx = tid + t * 256;
        int k   = idx >> 5;
        int c4  = (idx & 31) * 4;
        *(float4*)(ws + k * QWS + c4) = *(const float4*)(We + (size_t)k * HID + c4);
    }
    if (tid < 128) bs[tid] = bm1[tid];
    __syncthreads();

    const int lane = tid & 31;
    const int warp = tid >> 5;
    const int g    = lane >> 2;
    const int tig  = lane & 3;
    const int wm   = (warp >> 1) * 32;   // 0,32,64,96
    const int wn   = (warp & 1) * 64;    // 0,64

    float c[2][8][4];
#pragma unroll
    for (int mt = 0; mt < 2; mt++)
#pragma unroll
        for (int nt = 0; nt < 8; nt++)
#pragma unroll
            for (int i = 0; i < 4; i++) c[mt][nt][i] = 0.f;

#pragma unroll
    for (int kt = 0; kt < 2; kt++) {
        const int k0 = kt * 8;
        uint32_t a[2][4];
#pragma unroll
        for (int mt = 0; mt < 2; mt++) {
            int rb = wm + mt * 16;
            a[mt][0] = f2tf32(eas[(rb + g)     * QSS + k0 + tig]);
            a[mt][1] = f2tf32(eas[(rb + g + 8) * QSS + k0 + tig]);
            a[mt][2] = f2tf32(eas[(rb + g)     * QSS + k0 + tig + 4]);
            a[mt][3] = f2tf32(eas[(rb + g + 8) * QSS + k0 + tig + 4]);
        }
#pragma unroll
        for (int nt = 0; nt < 8; nt++) {
            int col = wn + nt * 8 + g;
            uint32_t b0 = f2tf32(ws[(k0 + tig)     * QWS + col]);
            uint32_t b1 = f2tf32(ws[(k0 + tig + 4) * QWS + col]);
#pragma unroll
            for (int mt = 0; mt < 2; mt++)
                mma_tf32(c[mt][nt], a[mt], b0, b1);
        }
    }

#pragma unroll
    for (int mt = 0; mt < 2; mt++) {
#pragma unroll
        for (int nt = 0; nt < 8; nt++) {
            int row0 = blockRow + wm + mt * 16 + g;
            int col0 = wn + nt * 8 + 2 * tig;
            if (row0 < E)
                *(__half2*)(q + (size_t)row0 * HID + col0) =
                    __floats2half2_rn(c[mt][nt][0] + bs[col0],
                                      c[mt][nt][1] + bs[col0 + 1]);
            int row1 = row0 + 8;
            if (row1 < E)
                *(__half2*)(q + (size_t)row1 * HID + col0) =
                    __floats2half2_rn(c[mt][nt][2] + bs[col0],
                                      c[mt][nt][3] + bs[col0 + 1]);
        }
    }
}

// ---------------------------------------------------------------------------
// agg[n,:] = sum_{e: dst=n} h[src_e,:]*dinv[src]*dinv[n] + h[n,:]*dinv[n]^2 + b
// fp16 gathers, fp32 (f32x2) accumulation. One warp per dst node. (R5 form.)
__global__ __launch_bounds__(256)
void gcn_aggregate(const __half* __restrict__ h, float* __restrict__ agg,
                   const int* __restrict__ rowoff, const int* __restrict__ csr_src,
                   const float* __restrict__ dinv, const float* __restrict__ bias,
                   int Nn)
{
    int lane = threadIdx.x & 31;
    int n = (blockIdx.x * blockDim.x + threadIdx.x) >> 5;
    if (n >= Nn) return;
    int c4 = lane * 4;

    float din = dinv[n];
    float wsl = din * din;
    uint2 hv = *(const uint2*)(h + (size_t)n * HID + c4);
    float2 h0 = __half22float2(*(const __half2*)&hv.x);
    float2 h1 = __half22float2(*(const __half2*)&hv.y);
    float4 bb = *(const float4*)(bias + c4);
    uint64_t acc0 = pack2(h0.x * wsl + bb.x, h0.y * wsl + bb.y);
    uint64_t acc1 = pack2(h1.x * wsl + bb.z, h1.y * wsl + bb.w);

    int beg = rowoff[n], end = rowoff[n + 1];
    for (int base = beg; base < end; base += 32) {
        int m = end - base;
        int s = 0;
        float ww = 0.f;
        if (lane < m) {
            s = __ldg(&csr_src[base + lane]);
            ww = dinv[s] * din;
        }
        int iters = min(m, 32);
#pragma unroll 4
        for (int j = 0; j < iters; j++) {
            int   sj = __shfl_sync(FULLMASK, s,  j);
            float wj = __shfl_sync(FULLMASK, ww, j);
            uint64_t wj2 = pack2(wj, wj);
            uint2 rv = *(const uint2*)(h + (size_t)sj * HID + c4);
            float2 r0 = __half22float2(*(const __half2*)&rv.x);
            float2 r1 = __half22float2(*(const __half2*)&rv.y);
            acc0 = fma2(pack2(r0.x, r0.y), wj2, acc0);
            acc1 = fma2(pack2(r1.x, r1.y), wj2, acc1);
        }
    }
    ulonglong2 outv;
    outv.x = acc0;
    outv.y = acc1;
    *(ulonglong2*)(agg + (size_t)n * HID + c4) = outv;
}

// ---------------------------------------------------------------------------
__global__ __launch_bounds__(256)
void bn_stats(const float* __restrict__ z, float* __restrict__ sum,
              float* __restrict__ sumsq, int Nn)
{
    __shared__ float sh[8][128];
    const int w  = threadIdx.x >> 5;
    const int c4 = (threadIdx.x & 31) * 4;

    float4 s = make_float4(0.f, 0.f, 0.f, 0.f);
    float4 q = make_float4(0.f, 0.f, 0.f, 0.f);
    for (int r = blockIdx.x * 8 + w; r < Nn; r += gridDim.x * 8) {
        float4 v = *(const float4*)(z + (size_t)r * HID + c4);
        s.x += v.x; s.y += v.y; s.z += v.z; s.w += v.w;
        q.x = fmaf(v.x, v.x, q.x);
        q.y = fmaf(v.y, v.y, q.y);
        q.z = fmaf(v.z, v.z, q.z);
        q.w = fmaf(v.w, v.w, q.w);
    }
    *(float4*)&sh[w][c4] = s;
    __syncthreads();
    if (threadIdx.x < 128) {
        int c = threadIdx.x;
        float t = sh[0][c] + sh[1][c] + sh[2][c] + sh[3][c]
                + sh[4][c] + sh[5][c] + sh[6][c] + sh[7][c];
        atomicAdd(&sum[c], t);
    }
    __syncthreads();
    *(float4*)&sh[w][c4] = q;
    __syncthreads();
    if (threadIdx.x < 128) {
        int c = threadIdx.x;
        float t = sh[0][c] + sh[1][c] + sh[2][c] + sh[3][c]
                + sh[4][c] + sh[5][c] + sh[6][c] + sh[7][c];
        atomicAdd(&sumsq[c], t);
    }
}

__global__ void bn_final(const float* __restrict__ sum, const float* __restrict__ sumsq,
                         const float* __restrict__ gamma, const float* __restrict__ beta,
                         float* __restrict__ scale, float* __restrict__ shift, int Nn)
{
    int i = threadIdx.x;
    if (i < HID) {
        float invN = 1.0f / (float)Nn;
        float mean = sum[i] * invN;
        float var  = sumsq[i] * invN - mean * mean;
        float sc   = gamma[i] * rsqrtf(var + 1e-5f);
        scale[i] = sc;
        shift[i] = beta[i] - mean * sc;
    }
}

// ---------------------------------------------------------------------------
// out[e] = relu(A[src] + B[dst] + q[e]) . Wm2 + bm2    (bm1 folded into q)
// fp16 gathers + coalesced q stream; tiny register footprint -> high occupancy.
__global__ __launch_bounds__(256)
void edge_mlp(const __half* __restrict__ A, const __half* __restrict__ B,
              const __half* __restrict__ q,
              const int* __restrict__ src, const int* __restrict__ dst,
              const float* __restrict__ Wm2, const float* __restrict__ bm2,
              float* __restrict__ out, int E)
{
    int lane = threadIdx.x & 31;
    int warp = (blockIdx.x * blockDim.x + threadIdx.x) >> 5;
    int nw   = (gridDim.x * blockDim.x) >> 5;
    int c4   = lane * 4;

    float4 w2 = *(const float4*)(Wm2 + c4);
    const float bm2v = __ldg(bm2);

    for (int base = warp * 32; base < E; base += nw * 32) {
        int m = min(32, E - base);
        int s = 0, d = 0;
        if (lane < m) {
            s = __ldg(&src[base + lane]);
            d = __ldg(&dst[base + lane]);
        }
        float res = 0.f;
        for (int j = 0; j < m; j++) {
            int sj = __shfl_sync(FULLMASK, s, j);
            int dj = __shfl_sync(FULLMASK, d, j);
            uint2 av2 = *(const uint2*)(A + (size_t)sj * HID + c4);
            uint2 bv2 = *(const uint2*)(B + (size_t)dj * HID + c4);
            uint2 qv2 = *(const uint2*)(q + (size_t)(base + j) * HID + c4);
            float2 a0 = __half22float2(*(const __half2*)&av2.x);
            float2 a1 = __half22float2(*(const __half2*)&av2.y);
            float2 b0 = __half22float2(*(const __half2*)&bv2.x);
            float2 b1 = __half22float2(*(const __half2*)&bv2.y);
            float2 q0 = __half22float2(*(const __half2*)&qv2.x);
            float2 q1 = __half22float2(*(const __half2*)&qv2.y);

            float f0 = fmaxf(a0.x + b0.x + q0.x, 0.f);
            float f1 = fmaxf(a0.y + b0.y + q0.y, 0.f);
            float f2 = fmaxf(a1.x + b1.x + q1.x, 0.f);
            float f3 = fmaxf(a1.y + b1.y + q1.y, 0.f);

            float p = f0 * w2.x + f1 * w2.y + f2 * w2.z + f3 * w2.w;
            float tot = warp_sum32(p);
            if (lane == j) res = tot + bm2v;
        }
        if (lane < m) out[base + lane] = res;   // coalesced 128B store
    }
}

// ---------------------------------------------------------------------------
extern "C" void kernel_launch(void* const* d_in, const int* in_sizes, int n_in,
                              void* d_out, int out_size)
{
    const float* x     = (const float*)d_in[0];
    const int*   ei    = (const int*)  d_in[1];
    const float* ea    = (const float*)d_in[2];
    const float* W1    = (const float*)d_in[3];
    const float* b1    = (const float*)d_in[4];
    const float* gamma = (const float*)d_in[5];
    const float* beta  = (const float*)d_in[6];
    const float* W2    = (const float*)d_in[7];
    const float* b2    = (const float*)d_in[8];
    const float* Wm1   = (const float*)d_in[9];
    const float* bm1   = (const float*)d_in[10];
    const float* Wm2   = (const float*)d_in[11];
    const float* bm2   = (const float*)d_in[12];
    float* out = (float*)d_out;

    const int Nn = in_sizes[0] / HID;
    const int E  = in_sizes[1] / 2;
    const int* src = ei;
    const int* dst = ei + E;

    float *buf0, *dinv, *sum, *sumsq, *scale, *shift;
    __half *h16, *A16, *B16, *q16;
    int *cnt, *rowoff, *cursor, *csr_src;
    cudaGetSymbolAddress((void**)&buf0,    g_buf0);
    cudaGetSymbolAddress((void**)&h16,     g_h16);
    cudaGetSymbolAddress((void**)&A16,     g_A16);
    cudaGetSymbolAddress((void**)&B16,     g_B16);
    cudaGetSymbolAddress((void**)&q16,     g_q16);
    cudaGetSymbolAddress((void**)&dinv,    g_dinv);
    cudaGetSymbolAddress((void**)&sum,     g_sum);
    cudaGetSymbolAddress((void**)&sumsq,   g_sumsq);
    cudaGetSymbolAddress((void**)&scale,   g_scale);
    cudaGetSymbolAddress((void**)&shift,   g_shift);
    cudaGetSymbolAddress((void**)&cnt,     g_cnt);
    cudaGetSymbolAddress((void**)&rowoff,  g_rowoff);
    cudaGetSymbolAddress((void**)&cursor,  g_cursor);
    cudaGetSymbolAddress((void**)&csr_src, g_csr_src);

    const int SMEM  = 2 * 128 * SMS * (int)sizeof(float);
    const int SMEMP = 128 * (SMS + WSS) * (int)sizeof(float);
    cudaFuncSetAttribute(gemm_tf32, cudaFuncAttributeMaxDynamicSharedMemorySize, SMEM);
    cudaFuncSetAttribute(gemm_proj, cudaFuncAttributeMaxDynamicSharedMemorySize, SMEMP);

    const int gN    = (Nn + 255) / 256;
    const int gE    = (E + 255) / 256;
    const int gGemm = (Nn + 127) / 128;
    const int gQ    = (E + 127) / 128;
    const int gAgg  = (Nn * 32 + 255) / 256;

    // CSR build (by dst) + degrees
    zero_aux<<<gN, 256>>>(cnt, sum, sumsq, Nn);
    hist_dst<<<gE, 256>>>(dst, cnt, E);
    scan_offsets<<<1, 1024>>>(cnt, rowoff, cursor, dinv, Nn);
    fill_csr<<<gE, 256>>>(src, dst, cursor, csr_src, E);

    // conv1: h1 = x @ W1 (fp16) ; agg1 = CSR gather + self-loop + b1 (fp32)
    gemm_tf32<<<gGemm, 256, SMEM>>>(x, W1, h16, Nn, nullptr, nullptr);
    gcn_aggregate<<<gAgg, 256>>>(h16, buf0, rowoff, csr_src, dinv, b1, Nn);

    // batchnorm stats (apply fused into next GEMM's A staging)
    bn_stats<<<512, 256>>>(buf0, sum, sumsq, Nn);
    bn_final<<<1, 128>>>(sum, sumsq, gamma, beta, scale, shift, Nn);

    // conv2: h2 = relu(bn(agg1)) @ W2 (fp16) ; agg2 (fp32, reuse buf0)
    gemm_tf32<<<gGemm, 256, SMEM>>>(buf0, W2, h16, Nn, scale, shift);
    gcn_aggregate<<<gAgg, 256>>>(h16, buf0, rowoff, csr_src, dinv, b2, Nn);

    // fused per-node projections: A16 = z2@Wm1[0:128], B16 = z2@Wm1[128:256]
    gemm_proj<<<gGemm, 512, SMEMP>>>(buf0, Wm1, A16, B16, Nn);

    // per-edge attr projection: q16 = ea @ Wm1[256:272] + bm1 (tensor cores)
    gemm_q<<<gQ, 256>>>(ea, Wm1 + 256 * HID, bm1, q16, E);

    // fused edge head
    edge_mlp<<<3200, 256>>>(A16, B16, q16, src, dst, Wm2, bm2, out, E);
}

// round 9
// speedup vs baseline: 1.0596x; 1.0316x over previous
#include <cuda_runtime.h>
#include <cuda_fp16.h>
#include <cstdint>

#define MAXN 50000
#define MAXE 800000
#define HID 128
#define FULLMASK 0xffffffffu

// ---- static scratch (no allocations allowed) ----
__device__ float  g_buf0[(size_t)MAXN * HID];   // fp32 aggregate outputs
__device__ __half g_h16 [(size_t)MAXN * HID];   // fp16 h1 then h2 (gather target)
__device__ __half g_A16 [(size_t)MAXN * HID];   // fp16 edge-head src projection
__device__ __half g_B16 [(size_t)MAXN * HID];   // fp16 edge-head dst projection
__device__ float  g_dinv[MAXN];
__device__ float  g_sum[HID];
__device__ float  g_sumsq[HID];
__device__ float  g_scale[HID];
__device__ float  g_shift[HID];
__device__ int    g_cnt[MAXN];
__device__ int    g_rowoff[MAXN + 1];
__device__ int    g_cursor[MAXN];
__device__ int    g_csr_src[MAXE];

// ---- packed f32x2 helpers (sm_103a FFMA2 path) ----
__device__ __forceinline__ uint64_t pack2(float lo, float hi)
{
    uint64_t r;
    asm("mov.b64 %0,{%1,%2};" : "=l"(r) : "f"(lo), "f"(hi));
    return r;
}
__device__ __forceinline__ void unpack2(uint64_t v, float& lo, float& hi)
{
    asm("mov.b64 {%0,%1},%2;" : "=f"(lo), "=f"(hi) : "l"(v));
}
__device__ __forceinline__ uint64_t fma2(uint64_t a, uint64_t b, uint64_t c)
{
    uint64_t d;
    asm("fma.rn.f32x2 %0,%1,%2,%3;" : "=l"(d) : "l"(a), "l"(b), "l"(c));
    return d;
}
__device__ __forceinline__ uint64_t add2(uint64_t a, uint64_t b)
{
    uint64_t d;
    asm("add.rn.f32x2 %0,%1,%2;" : "=l"(d) : "l"(a), "l"(b));
    return d;
}

// ---------------------------------------------------------------------------
__global__ void zero_aux(int* __restrict__ cnt, float* __restrict__ sum,
                         float* __restrict__ sumsq, int n)
{
    int i = blockIdx.x * blockDim.x + threadIdx.x;
    if (i < n) cnt[i] = 0;
    if (i < HID) { sum[i] = 0.0f; sumsq[i] = 0.0f; }
}

__global__ void hist_dst(const int* __restrict__ dst, int* __restrict__ cnt, int E)
{
    int i = blockIdx.x * blockDim.x + threadIdx.x;
    if (i < E) atomicAdd(&cnt[dst[i]], 1);
}

// Single-block coalesced tiled exclusive scan. Emits rowoff, cursor, dinv.
__global__ __launch_bounds__(1024)
void scan_offsets(const int* __restrict__ cnt, int* __restrict__ rowoff,
                  int* __restrict__ cursor, float* __restrict__ dinv, int n)
{
    __shared__ int warp_sums[32];
    const int t = threadIdx.x;
    const int lane = t & 31;
    const int w = t >> 5;
    int carry = 0;

    for (int base = 0; base < n; base += 1024) {
        int i = base + t;
        int c = (i < n) ? cnt[i] : 0;
        int v = c;
#pragma unroll
        for (int o = 1; o < 32; o <<= 1) {
            int u = __shfl_up_sync(FULLMASK, v, o);
            if (lane >= o) v += u;
        }
        if (lane == 31) warp_sums[w] = v;
        __syncthreads();
        if (w == 0) {
            int sv = warp_sums[lane];
#pragma unroll
            for (int o = 1; o < 32; o <<= 1) {
                int u = __shfl_up_sync(FULLMASK, sv, o);
                if (lane >= o) sv += u;
            }
            warp_sums[lane] = sv;
        }
        __syncthreads();
        int excl = carry + (w ? warp_sums[w - 1] : 0) + v - c;
        if (i < n) {
            rowoff[i] = excl;
            cursor[i] = excl;
            dinv[i]   = rsqrtf((float)c + 1.0f);
        }
        int tile_total = warp_sums[31];
        __syncthreads();
        carry += tile_total;
    }
    if (t == 0) rowoff[n] = carry;
}

__global__ void fill_csr(const int* __restrict__ src, const int* __restrict__ dst,
                         int* __restrict__ cursor, int* __restrict__ csr_src, int E)
{
    int e = blockIdx.x * blockDim.x + threadIdx.x;
    if (e < E) {
        int d = dst[e];
        int pos = atomicAdd(&cursor[d], 1);
        csr_src[pos] = src[e];
    }
}

// ---------------------------------------------------------------------------
// tf32 tensor-core GEMM with 3xTF32 error compensation. Output fp16.
#define SMS 136
#define WSS 264

__device__ __forceinline__ uint32_t f2tf32(float x)
{
    uint32_t r;
    asm("cvt.rna.tf32.f32 %0, %1;" : "=r"(r) : "f"(x));
    return r;
}

__device__ __forceinline__ void mma_tf32(float c[4], const uint32_t a[4],
                                         uint32_t b0, uint32_t b1)
{
    asm volatile(
        "mma.sync.aligned.m16n8k8.row.col.f32.tf32.tf32.f32 "
        "{%0,%1,%2,%3},{%4,%5,%6,%7},{%8,%9},{%0,%1,%2,%3};"
        : "+f"(c[0]), "+f"(c[1]), "+f"(c[2]), "+f"(c[3])
        : "r"(a[0]), "r"(a[1]), "r"(a[2]), "r"(a[3]), "r"(b0), "r"(b1));
}

// C16[M,128] = f(A)[M,128] @ W[128,128]; f = optional scale/shift+relu.
__global__ __launch_bounds__(256)
void gemm_tf32(const float* __restrict__ A, const float* __restrict__ W,
               __half* __restrict__ C, int M,
               const float* __restrict__ pre_scale,
               const float* __restrict__ pre_shift)
{
    extern __shared__ float smem[];
    float* As = smem;              // [128][SMS]
    float* Ws = smem + 128 * SMS;  // [128][SMS]

    const int tid = threadIdx.x;
    const int blockRow = blockIdx.x * 128;
    const bool do_pre = (pre_scale != nullptr);

#pragma unroll
    for (int t = 0; t < 16; t++) {
        int idx = tid + t * 256;
        int row = idx >> 5;
        int c4  = (idx & 31) * 4;
        int gr  = blockRow + row;
        float4 av = (gr < M) ? *(const float4*)(A + (size_t)gr * HID + c4)
                             : make_float4(0.f, 0.f, 0.f, 0.f);
        if (do_pre) {
            float4 sc = *(const float4*)(pre_scale + c4);
            float4 sh = *(const float4*)(pre_shift + c4);
            av.x = fmaxf(av.x * sc.x + sh.x, 0.f);
            av.y = fmaxf(av.y * sc.y + sh.y, 0.f);
            av.z = fmaxf(av.z * sc.z + sh.z, 0.f);
            av.w = fmaxf(av.w * sc.w + sh.w, 0.f);
        }
        *(float4*)(As + row * SMS + c4) = av;
        *(float4*)(Ws + row * SMS + c4) = *(const float4*)(W + (size_t)row * HID + c4);
    }
    __syncthreads();

    const int lane = tid & 31;
    const int warp = tid >> 5;
    const int g    = lane >> 2;
    const int tig  = lane & 3;
    const int wm   = (warp >> 1) * 32;
    const int wn   = (warp & 1) * 64;

    float c[2][8][4];
#pragma unroll
    for (int mt = 0; mt < 2; mt++)
#pragma unroll
        for (int nt = 0; nt < 8; nt++)
#pragma unroll
            for (int i = 0; i < 4; i++) c[mt][nt][i] = 0.f;

#pragma unroll
    for (int kt = 0; kt < 16; kt++) {
        const int k0 = kt * 8;
        uint32_t ahi[2][4], alo[2][4];
#pragma unroll
        for (int mt = 0; mt < 2; mt++) {
            int rb = wm + mt * 16;
            float a0 = As[(rb + g)     * SMS + k0 + tig];
            float a1 = As[(rb + g + 8) * SMS + k0 + tig];
            float a2 = As[(rb + g)     * SMS + k0 + tig + 4];
            float a3 = As[(rb + g + 8) * SMS + k0 + tig + 4];
            ahi[mt][0] = f2tf32(a0); alo[mt][0] = f2tf32(a0 - __uint_as_float(ahi[mt][0]));
            ahi[mt][1] = f2tf32(a1); alo[mt][1] = f2tf32(a1 - __uint_as_float(ahi[mt][1]));
            ahi[mt][2] = f2tf32(a2); alo[mt][2] = f2tf32(a2 - __uint_as_float(ahi[mt][2]));
            ahi[mt][3] = f2tf32(a3); alo[mt][3] = f2tf32(a3 - __uint_as_float(ahi[mt][3]));
        }
#pragma unroll
        for (int nt = 0; nt < 8; nt++) {
            int col = wn + nt * 8 + g;
            float b0 = Ws[(k0 + tig)     * SMS + col];
            float b1 = Ws[(k0 + tig + 4) * SMS + col];
            uint32_t bh0 = f2tf32(b0), bh1 = f2tf32(b1);
            uint32_t bl0 = f2tf32(b0 - __uint_as_float(bh0));
            uint32_t bl1 = f2tf32(b1 - __uint_as_float(bh1));
#pragma unroll
            for (int mt = 0; mt < 2; mt++) {
                mma_tf32(c[mt][nt], ahi[mt], bh0, bh1);
                mma_tf32(c[mt][nt], ahi[mt], bl0, bl1);
                mma_tf32(c[mt][nt], alo[mt], bh0, bh1);
            }
        }
    }

#pragma unroll
    for (int mt = 0; mt < 2; mt++) {
#pragma unroll
        for (int nt = 0; nt < 8; nt++) {
            int row0 = blockRow + wm + mt * 16 + g;
            int col0 = wn + nt * 8 + 2 * tig;
            if (row0 < M)
                *(__half2*)(C + (size_t)row0 * HID + col0) =
                    __floats2half2_rn(c[mt][nt][0], c[mt][nt][1]);
            int row1 = row0 + 8;
            if (row1 < M)
                *(__half2*)(C + (size_t)row1 * HID + col0) =
                    __floats2half2_rn(c[mt][nt][2], c[mt][nt][3]);
        }
    }
}

// Fused projection GEMM: C0 = A @ W[0:128], C1 = A @ W[128:256], fp16 outputs.
__global__ __launch_bounds__(512)
void gemm_proj(const float* __restrict__ A, const float* __restrict__ W,
               __half* __restrict__ C0, __half* __restrict__ C1, int M)
{
    extern __shared__ float smem[];
    float* As = smem;              // [128][SMS]
    float* Ws = smem + 128 * SMS;  // [128][WSS]

    const int tid = threadIdx.x;
    const int blockRow = blockIdx.x * 128;

#pragma unroll
    for (int t = 0; t < 8; t++) {
        int idx = tid + t * 512;
        int row = idx >> 5;
        int c4  = (idx & 31) * 4;
        int gr  = blockRow + row;
        float4 av = (gr < M) ? *(const float4*)(A + (size_t)gr * HID + c4)
                             : make_float4(0.f, 0.f, 0.f, 0.f);
        *(float4*)(As + row * SMS + c4) = av;
    }
#pragma unroll
    for (int t = 0; t < 16; t++) {
        int idx = tid + t * 512;
        int r   = idx >> 5;
        int c4  = (idx & 31) * 4;
        int k    = r & 127;
        int half = r >> 7;
        *(float4*)(Ws + k * WSS + half * 128 + c4) =
            *(const float4*)(W + (size_t)r * HID + c4);
    }
    __syncthreads();

    const int lane = tid & 31;
    const int warp = tid >> 5;
    const int g    = lane >> 2;
    const int tig  = lane & 3;
    const int wm   = (warp >> 2) * 32;
    const int wn   = (warp & 3) * 64;

    float c[2][8][4];
#pragma unroll
    for (int mt = 0; mt < 2; mt++)
#pragma unroll
        for (int nt = 0; nt < 8; nt++)
#pragma unroll
            for (int i = 0; i < 4; i++) c[mt][nt][i] = 0.f;

#pragma unroll
    for (int kt = 0; kt < 16; kt++) {
        const int k0 = kt * 8;
        uint32_t ahi[2][4], alo[2][4];
#pragma unroll
        for (int mt = 0; mt < 2; mt++) {
            int rb = wm + mt * 16;
            float a0 = As[(rb + g)     * SMS + k0 + tig];
            float a1 = As[(rb + g + 8) * SMS + k0 + tig];
            float a2 = As[(rb + g)     * SMS + k0 + tig + 4];
            float a3 = As[(rb + g + 8) * SMS + k0 + tig + 4];
            ahi[mt][0] = f2tf32(a0); alo[mt][0] = f2tf32(a0 - __uint_as_float(ahi[mt][0]));
            ahi[mt][1] = f2tf32(a1); alo[mt][1] = f2tf32(a1 - __uint_as_float(ahi[mt][1]));
            ahi[mt][2] = f2tf32(a2); alo[mt][2] = f2tf32(a2 - __uint_as_float(ahi[mt][2]));
            ahi[mt][3] = f2tf32(a3); alo[mt][3] = f2tf32(a3 - __uint_as_float(ahi[mt][3]));
        }
#pragma unroll
        for (int nt = 0; nt < 8; nt++) {
            int col = wn + nt * 8 + g;
            float b0 = Ws[(k0 + tig)     * WSS + col];
            float b1 = Ws[(k0 + tig + 4) * WSS + col];
            uint32_t bh0 = f2tf32(b0), bh1 = f2tf32(b1);
            uint32_t bl0 = f2tf32(b0 - __uint_as_float(bh0));
            uint32_t bl1 = f2tf32(b1 - __uint_as_float(bh1));
#pragma unroll
            for (int mt = 0; mt < 2; mt++) {
                mma_tf32(c[mt][nt], ahi[mt], bh0, bh1);
                mma_tf32(c[mt][nt], ahi[mt], bl0, bl1);
                mma_tf32(c[mt][nt], alo[mt], bh0, bh1);
            }
        }
    }

    __half* Cb = (wn < 128) ? C0 : C1;
    const int cbase = (wn < 128) ? wn : wn - 128;
#pragma unroll
    for (int mt = 0; mt < 2; mt++) {
#pragma unroll
        for (int nt = 0; nt < 8; nt++) {
            int row0 = blockRow + wm + mt * 16 + g;
            int col0 = cbase + nt * 8 + 2 * tig;
            if (row0 < M)
                *(__half2*)(Cb + (size_t)row0 * HID + col0) =
                    __floats2half2_rn(c[mt][nt][0], c[mt][nt][1]);
            int row1 = row0 + 8;
            if (row1 < M)
                *(__half2*)(Cb + (size_t)row1 * HID + col0) =
                    __floats2half2_rn(c[mt][nt][2], c[mt][nt][3]);
        }
    }
}

// ---------------------------------------------------------------------------
// agg[n,:] = sum_{e: dst=n} h[src_e,:]*dinv[src]*dinv[n] + h[n,:]*dinv[n]^2 + b
// fp16 gathers, fp32 (f32x2) accumulation. One warp per dst node. (R5 form.)
__global__ __launch_bounds__(256)
void gcn_aggregate(const __half* __restrict__ h, float* __restrict__ agg,
                   const int* __restrict__ rowoff, const int* __restrict__ csr_src,
                   const float* __restrict__ dinv, const float* __restrict__ bias,
                   int Nn)
{
    int lane = threadIdx.x & 31;
    int n = (blockIdx.x * blockDim.x + threadIdx.x) >> 5;
    if (n >= Nn) return;
    int c4 = lane * 4;

    float din = dinv[n];
    float wsl = din * din;
    uint2 hv = *(const uint2*)(h + (size_t)n * HID + c4);
    float2 h0 = __half22float2(*(const __half2*)&hv.x);
    float2 h1 = __half22float2(*(const __half2*)&hv.y);
    float4 bb = *(const float4*)(bias + c4);
    uint64_t acc0 = pack2(h0.x * wsl + bb.x, h0.y * wsl + bb.y);
    uint64_t acc1 = pack2(h1.x * wsl + bb.z, h1.y * wsl + bb.w);

    int beg = rowoff[n], end = rowoff[n + 1];
    for (int base = beg; base < end; base += 32) {
        int m = end - base;
        int s = 0;
        float ww = 0.f;
        if (lane < m) {
            s = __ldg(&csr_src[base + lane]);
            ww = dinv[s] * din;
        }
        int iters = min(m, 32);
#pragma unroll 4
        for (int j = 0; j < iters; j++) {
            int   sj = __shfl_sync(FULLMASK, s,  j);
            float wj = __shfl_sync(FULLMASK, ww, j);
            uint64_t wj2 = pack2(wj, wj);
            uint2 rv = *(const uint2*)(h + (size_t)sj * HID + c4);
            float2 r0 = __half22float2(*(const __half2*)&rv.x);
            float2 r1 = __half22float2(*(const __half2*)&rv.y);
            acc0 = fma2(pack2(r0.x, r0.y), wj2, acc0);
            acc1 = fma2(pack2(r1.x, r1.y), wj2, acc1);
        }
    }
    ulonglong2 outv;
    outv.x = acc0;
    outv.y = acc1;
    *(ulonglong2*)(agg + (size_t)n * HID + c4) = outv;
}

// ---------------------------------------------------------------------------
__global__ __launch_bounds__(256)
void bn_stats(const float* __restrict__ z, float* __restrict__ sum,
              float* __restrict__ sumsq, int Nn)
{
    __shared__ float sh[8][128];
    const int w  = threadIdx.x >> 5;
    const int c4 = (threadIdx.x & 31) * 4;

    float4 s = make_float4(0.f, 0.f, 0.f, 0.f);
    float4 q = make_float4(0.f, 0.f, 0.f, 0.f);
    for (int r = blockIdx.x * 8 + w; r < Nn; r += gridDim.x * 8) {
        float4 v = *(const float4*)(z + (size_t)r * HID + c4);
        s.x += v.x; s.y += v.y; s.z += v.z; s.w += v.w;
        q.x = fmaf(v.x, v.x, q.x);
        q.y = fmaf(v.y, v.y, q.y);
        q.z = fmaf(v.z, v.z, q.z);
        q.w = fmaf(v.w, v.w, q.w);
    }
    *(float4*)&sh[w][c4] = s;
    __syncthreads();
    if (threadIdx.x < 128) {
        int c = threadIdx.x;
        float t = sh[0][c] + sh[1][c] + sh[2][c] + sh[3][c]
                + sh[4][c] + sh[5][c] + sh[6][c] + sh[7][c];
        atomicAdd(&sum[c], t);
    }
    __syncthreads();
    *(float4*)&sh[w][c4] = q;
    __syncthreads();
    if (threadIdx.x < 128) {
        int c = threadIdx.x;
        float t = sh[0][c] + sh[1][c] + sh[2][c] + sh[3][c]
                + sh[4][c] + sh[5][c] + sh[6][c] + sh[7][c];
        atomicAdd(&sumsq[c], t);
    }
}

__global__ void bn_final(const float* __restrict__ sum, const float* __restrict__ sumsq,
                         const float* __restrict__ gamma, const float* __restrict__ beta,
                         float* __restrict__ scale, float* __restrict__ shift, int Nn)
{
    int i = threadIdx.x;
    if (i < HID) {
        float invN = 1.0f / (float)Nn;
        float mean = sum[i] * invN;
        float var  = sumsq[i] * invN - mean * mean;
        float sc   = gamma[i] * rsqrtf(var + 1e-5f);
        scale[i] = sc;
        shift[i] = beta[i] - mean * sc;
    }
}

// ---------------------------------------------------------------------------
// out[e] = relu(A[src] + B[dst] + edge_attr[e]@We + bm1) . Wm2 + bm2
// fp16 A/B gathers; We in registers (f32x2); per-edge partials staged in smem
// (conflict-free 33-stride), one transpose-sum per 32 edges -> no per-edge
// butterfly, iterations fully independent.
__global__ __launch_bounds__(256)
void edge_mlp(const __half* __restrict__ A, const __half* __restrict__ B,
              const int* __restrict__ src, const int* __restrict__ dst,
              const float* __restrict__ ea, const float* __restrict__ We,  // [16,128]
              const float* __restrict__ bm1, const float* __restrict__ Wm2,
              const float* __restrict__ bm2, float* __restrict__ out, int E)
{
    __shared__ float red[8][32][33];
    int lane  = threadIdx.x & 31;
    int wloc  = threadIdx.x >> 5;
    int warp  = (blockIdx.x * blockDim.x + threadIdx.x) >> 5;
    int nw    = (gridDim.x * blockDim.x) >> 5;
    int c4    = lane * 4;

    uint64_t wp0[16], wp1[16];
#pragma unroll
    for (int k = 0; k < 16; k++) {
        ulonglong2 wv = *(const ulonglong2*)(We + (size_t)k * HID + c4);
        wp0[k] = wv.x;
        wp1[k] = wv.y;
    }
    ulonglong2 bv2 = *(const ulonglong2*)(bm1 + c4);
    const uint64_t bias0 = bv2.x, bias1 = bv2.y;
    float4 w2 = *(const float4*)(Wm2 + c4);
    const float bm2v = __ldg(bm2);

    for (int base = warp * 32; base < E; base += nw * 32) {
        int m = min(32, E - base);
        int s = 0, d = 0;
        if (lane < m) {
            s = __ldg(&src[base + lane]);
            d = __ldg(&dst[base + lane]);
        }
        for (int j = 0; j < m; j++) {
            int sj = __shfl_sync(FULLMASK, s, j);
            int dj = __shfl_sync(FULLMASK, d, j);
            uint2 av2 = *(const uint2*)(A + (size_t)sj * HID + c4);
            uint2 bvv = *(const uint2*)(B + (size_t)dj * HID + c4);
            float2 a0 = __half22float2(*(const __half2*)&av2.x);
            float2 a1 = __half22float2(*(const __half2*)&av2.y);
            float2 b0 = __half22float2(*(const __half2*)&bvv.x);
            float2 b1 = __half22float2(*(const __half2*)&bvv.y);
            uint64_t acc0 = add2(pack2(a0.x + b0.x, a0.y + b0.y), bias0);
            uint64_t acc1 = add2(pack2(a1.x + b1.x, a1.y + b1.y), bias1);

            const float4* eap = (const float4*)(ea + (size_t)(base + j) * 16);
#pragma unroll
            for (int gq = 0; gq < 4; gq++) {
                float4 e4 = __ldg(&eap[gq]);   // uniform across warp -> broadcast
                uint64_t ex;
                ex = pack2(e4.x, e4.x);
                acc0 = fma2(wp0[gq * 4 + 0], ex, acc0);
                acc1 = fma2(wp1[gq * 4 + 0], ex, acc1);
                ex = pack2(e4.y, e4.y);
                acc0 = fma2(wp0[gq * 4 + 1], ex, acc0);
                acc1 = fma2(wp1[gq * 4 + 1], ex, acc1);
                ex = pack2(e4.z, e4.z);
                acc0 = fma2(wp0[gq * 4 + 2], ex, acc0);
                acc1 = fma2(wp1[gq * 4 + 2], ex, acc1);
                ex = pack2(e4.w, e4.w);
                acc0 = fma2(wp0[gq * 4 + 3], ex, acc0);
                acc1 = fma2(wp1[gq * 4 + 3], ex, acc1);
            }
            float f0, f1, f2, f3;
            unpack2(acc0, f0, f1);
            unpack2(acc1, f2, f3);
            f0 = fmaxf(f0, 0.f);
            f1 = fmaxf(f1, 0.f);
            f2 = fmaxf(f2, 0.f);
            f3 = fmaxf(f3, 0.f);

            // per-lane partial of edge j's dot product -> smem (no butterfly)
            red[wloc][j][lane] = f0 * w2.x + f1 * w2.y + f2 * w2.z + f3 * w2.w;
        }
        __syncwarp();
        if (lane < m) {
            const float* r = &red[wloc][lane][0];
            float t0 = 0.f, t1 = 0.f, t2 = 0.f, t3 = 0.f;
#pragma unroll
            for (int k = 0; k < 32; k += 4) {   // 33-stride rows: conflict-free
                t0 += r[k];
                t1 += r[k + 1];
                t2 += r[k + 2];
                t3 += r[k + 3];
            }
            out[base + lane] = (t0 + t1) + (t2 + t3) + bm2v;   // coalesced store
        }
        __syncwarp();
    }
}

// ---------------------------------------------------------------------------
extern "C" void kernel_launch(void* const* d_in, const int* in_sizes, int n_in,
                              void* d_out, int out_size)
{
    const float* x     = (const float*)d_in[0];
    const int*   ei    = (const int*)  d_in[1];
    const float* ea    = (const float*)d_in[2];
    const float* W1    = (const float*)d_in[3];
    const float* b1    = (const float*)d_in[4];
    const float* gamma = (const float*)d_in[5];
    const float* beta  = (const float*)d_in[6];
    const float* W2    = (const float*)d_in[7];
    const float* b2    = (const float*)d_in[8];
    const float* Wm1   = (const float*)d_in[9];
    const float* bm1   = (const float*)d_in[10];
    const float* Wm2   = (const float*)d_in[11];
    const float* bm2   = (const float*)d_in[12];
    float* out = (float*)d_out;

    const int Nn = in_sizes[0] / HID;
    const int E  = in_sizes[1] / 2;
    const int* src = ei;
    const int* dst = ei + E;

    float *buf0, *dinv, *sum, *sumsq, *scale, *shift;
    __half *h16, *A16, *B16;
    int *cnt, *rowoff, *cursor, *csr_src;
    cudaGetSymbolAddress((void**)&buf0,    g_buf0);
    cudaGetSymbolAddress((void**)&h16,     g_h16);
    cudaGetSymbolAddress((void**)&A16,     g_A16);
    cudaGetSymbolAddress((void**)&B16,     g_B16);
    cudaGetSymbolAddress((void**)&dinv,    g_dinv);
    cudaGetSymbolAddress((void**)&sum,     g_sum);
    cudaGetSymbolAddress((void**)&sumsq,   g_sumsq);
    cudaGetSymbolAddress((void**)&scale,   g_scale);
    cudaGetSymbolAddress((void**)&shift,   g_shift);
    cudaGetSymbolAddress((void**)&cnt,     g_cnt);
    cudaGetSymbolAddress((void**)&rowoff,  g_rowoff);
    cudaGetSymbolAddress((void**)&cursor,  g_cursor);
    cudaGetSymbolAddress((void**)&csr_src, g_csr_src);

    const int SMEM  = 2 * 128 * SMS * (int)sizeof(float);
    const int SMEMP = 128 * (SMS + WSS) * (int)sizeof(float);
    cudaFuncSetAttribute(gemm_tf32, cudaFuncAttributeMaxDynamicSharedMemorySize, SMEM);
    cudaFuncSetAttribute(gemm_proj, cudaFuncAttributeMaxDynamicSharedMemorySize, SMEMP);

    const int gN    = (Nn + 255) / 256;
    const int gE    = (E + 255) / 256;
    const int gGemm = (Nn + 127) / 128;
    const int gAgg  = (Nn * 32 + 255) / 256;

    // CSR build (by dst) + degrees
    zero_aux<<<gN, 256>>>(cnt, sum, sumsq, Nn);
    hist_dst<<<gE, 256>>>(dst, cnt, E);
    scan_offsets<<<1, 1024>>>(cnt, rowoff, cursor, dinv, Nn);
    fill_csr<<<gE, 256>>>(src, dst, cursor, csr_src, E);

    // conv1: h1 = x @ W1 (fp16) ; agg1 = CSR gather + self-loop + b1 (fp32)
    gemm_tf32<<<gGemm, 256, SMEM>>>(x, W1, h16, Nn, nullptr, nullptr);
    gcn_aggregate<<<gAgg, 256>>>(h16, buf0, rowoff, csr_src, dinv, b1, Nn);

    // batchnorm stats (apply fused into next GEMM's A staging)
    bn_stats<<<512, 256>>>(buf0, sum, sumsq, Nn);
    bn_final<<<1, 128>>>(sum, sumsq, gamma, beta, scale, shift, Nn);

    // conv2: h2 = relu(bn(agg1)) @ W2 (fp16) ; agg2 (fp32, reuse buf0)
    gemm_tf32<<<gGemm, 256, SMEM>>>(buf0, W2, h16, Nn, scale, shift);
    gcn_aggregate<<<gAgg, 256>>>(h16, buf0, rowoff, csr_src, dinv, b2, Nn);

    // fused per-node projections: A16 = z2@Wm1[0:128], B16 = z2@Wm1[128:256]
    gemm_proj<<<gGemm, 512, SMEMP>>>(buf0, Wm1, A16, B16, Nn);

    // fused edge head
    edge_mlp<<<2048, 256>>>(A16, B16, src, dst, ea, Wm1 + 256 * HID,
                            bm1, Wm2, bm2, out, E);
}

// round 10
// speedup vs baseline: 1.2758x; 1.2041x over previous
#include <cuda_runtime.h>
#include <cuda_fp16.h>
#include <cstdint>

#define MAXN 50000
#define MAXE 800000
#define HID 128
#define FULLMASK 0xffffffffu

// ---- static scratch (no allocations allowed) ----
__device__ float  g_buf0[(size_t)MAXN * HID];   // fp32 aggregate outputs
__device__ __half g_h16 [(size_t)MAXN * HID];   // fp16 h1 then h2 (gather target)
__device__ __half g_A16 [(size_t)MAXN * HID];   // fp16 edge-head src projection
__device__ __half g_B16 [(size_t)MAXN * HID];   // fp16 edge-head dst projection
__device__ float  g_dinv[MAXN];
__device__ float  g_sum[HID];
__device__ float  g_sumsq[HID];
__device__ float  g_scale[HID];
__device__ float  g_shift[HID];
__device__ int    g_cnt[MAXN];
__device__ int    g_rowoff[MAXN + 1];
__device__ int    g_cursor[MAXN];
__device__ int    g_csr_src[MAXE];

// ---- packed f32x2 helpers (sm_103a FFMA2 path) ----
__device__ __forceinline__ uint64_t pack2(float lo, float hi)
{
    uint64_t r;
    asm("mov.b64 %0,{%1,%2};" : "=l"(r) : "f"(lo), "f"(hi));
    return r;
}
__device__ __forceinline__ void unpack2(uint64_t v, float& lo, float& hi)
{
    asm("mov.b64 {%0,%1},%2;" : "=f"(lo), "=f"(hi) : "l"(v));
}
__device__ __forceinline__ uint64_t fma2(uint64_t a, uint64_t b, uint64_t c)
{
    uint64_t d;
    asm("fma.rn.f32x2 %0,%1,%2,%3;" : "=l"(d) : "l"(a), "l"(b), "l"(c));
    return d;
}
__device__ __forceinline__ uint64_t add2(uint64_t a, uint64_t b)
{
    uint64_t d;
    asm("add.rn.f32x2 %0,%1,%2;" : "=l"(d) : "l"(a), "l"(b));
    return d;
}

// ---------------------------------------------------------------------------
__global__ void zero_aux(int* __restrict__ cnt, float* __restrict__ sum,
                         float* __restrict__ sumsq, int n)
{
    int i = blockIdx.x * blockDim.x + threadIdx.x;
    if (i < n) cnt[i] = 0;
    if (i < HID) { sum[i] = 0.0f; sumsq[i] = 0.0f; }
}

__global__ void hist_dst(const int* __restrict__ dst, int* __restrict__ cnt, int E)
{
    int i = blockIdx.x * blockDim.x + threadIdx.x;
    if (i < E) atomicAdd(&cnt[dst[i]], 1);
}

// Single-block coalesced tiled exclusive scan. Emits rowoff, cursor, dinv.
__global__ __launch_bounds__(1024)
void scan_offsets(const int* __restrict__ cnt, int* __restrict__ rowoff,
                  int* __restrict__ cursor, float* __restrict__ dinv, int n)
{
    __shared__ int warp_sums[32];
    const int t = threadIdx.x;
    const int lane = t & 31;
    const int w = t >> 5;
    int carry = 0;

    for (int base = 0; base < n; base += 1024) {
        int i = base + t;
        int c = (i < n) ? cnt[i] : 0;
        int v = c;
#pragma unroll
        for (int o = 1; o < 32; o <<= 1) {
            int u = __shfl_up_sync(FULLMASK, v, o);
            if (lane >= o) v += u;
        }
        if (lane == 31) warp_sums[w] = v;
        __syncthreads();
        if (w == 0) {
            int sv = warp_sums[lane];
#pragma unroll
            for (int o = 1; o < 32; o <<= 1) {
                int u = __shfl_up_sync(FULLMASK, sv, o);
                if (lane >= o) sv += u;
            }
            warp_sums[lane] = sv;
        }
        __syncthreads();
        int excl = carry + (w ? warp_sums[w - 1] : 0) + v - c;
        if (i < n) {
            rowoff[i] = excl;
            cursor[i] = excl;
            dinv[i]   = rsqrtf((float)c + 1.0f);
        }
        int tile_total = warp_sums[31];
        __syncthreads();
        carry += tile_total;
    }
    if (t == 0) rowoff[n] = carry;
}

__global__ void fill_csr(const int* __restrict__ src, const int* __restrict__ dst,
                         int* __restrict__ cursor, int* __restrict__ csr_src, int E)
{
    int e = blockIdx.x * blockDim.x + threadIdx.x;
    if (e < E) {
        int d = dst[e];
        int pos = atomicAdd(&cursor[d], 1);
        csr_src[pos] = src[e];
    }
}

// ---------------------------------------------------------------------------
// 1xTF32 tensor-core GEMM. Operands pre-rounded to tf32 at smem staging
// (one cvt per element); inner loop is pure LDS + MMA. Output fp16.
// Error budget: tf32 mantissa == fp16 mantissa (10 bits); adds ~2e-4
// independent error on top of the fp16-storage error -> total ~5e-4 < 1e-3.
#define SMS 136
#define WSS 264

__device__ __forceinline__ uint32_t f2tf32(float x)
{
    uint32_t r;
    asm("cvt.rna.tf32.f32 %0, %1;" : "=r"(r) : "f"(x));
    return r;
}
__device__ __forceinline__ float tf32r(float x)   // round to tf32, keep as float
{
    return __uint_as_float(f2tf32(x));
}

__device__ __forceinline__ void mma_tf32(float c[4], const uint32_t a[4],
                                         uint32_t b0, uint32_t b1)
{
    asm volatile(
        "mma.sync.aligned.m16n8k8.row.col.f32.tf32.tf32.f32 "
        "{%0,%1,%2,%3},{%4,%5,%6,%7},{%8,%9},{%0,%1,%2,%3};"
        : "+f"(c[0]), "+f"(c[1]), "+f"(c[2]), "+f"(c[3])
        : "r"(a[0]), "r"(a[1]), "r"(a[2]), "r"(a[3]), "r"(b0), "r"(b1));
}

// C16[M,128] = f(A)[M,128] @ W[128,128]; f = optional scale/shift+relu.
__global__ __launch_bounds__(256)
void gemm_tf32(const float* __restrict__ A, const float* __restrict__ W,
               __half* __restrict__ C, int M,
               const float* __restrict__ pre_scale,
               const float* __restrict__ pre_shift)
{
    extern __shared__ float smem[];
    float* As = smem;              // [128][SMS], tf32-rounded
    float* Ws = smem + 128 * SMS;  // [128][SMS], tf32-rounded

    const int tid = threadIdx.x;
    const int blockRow = blockIdx.x * 128;
    const bool do_pre = (pre_scale != nullptr);

#pragma unroll
    for (int t = 0; t < 16; t++) {
        int idx = tid + t * 256;
        int row = idx >> 5;
        int c4  = (idx & 31) * 4;
        int gr  = blockRow + row;
        float4 av = (gr < M) ? *(const float4*)(A + (size_t)gr * HID + c4)
                             : make_float4(0.f, 0.f, 0.f, 0.f);
        if (do_pre) {
            float4 sc = *(const float4*)(pre_scale + c4);
            float4 sh = *(const float4*)(pre_shift + c4);
            av.x = fmaxf(av.x * sc.x + sh.x, 0.f);
            av.y = fmaxf(av.y * sc.y + sh.y, 0.f);
            av.z = fmaxf(av.z * sc.z + sh.z, 0.f);
            av.w = fmaxf(av.w * sc.w + sh.w, 0.f);
        }
        av.x = tf32r(av.x); av.y = tf32r(av.y);
        av.z = tf32r(av.z); av.w = tf32r(av.w);
        *(float4*)(As + row * SMS + c4) = av;
        float4 wv = *(const float4*)(W + (size_t)row * HID + c4);
        wv.x = tf32r(wv.x); wv.y = tf32r(wv.y);
        wv.z = tf32r(wv.z); wv.w = tf32r(wv.w);
        *(float4*)(Ws + row * SMS + c4) = wv;
    }
    __syncthreads();

    const int lane = tid & 31;
    const int warp = tid >> 5;
    const int g    = lane >> 2;
    const int tig  = lane & 3;
    const int wm   = (warp >> 1) * 32;
    const int wn   = (warp & 1) * 64;

    float c[2][8][4];
#pragma unroll
    for (int mt = 0; mt < 2; mt++)
#pragma unroll
        for (int nt = 0; nt < 8; nt++)
#pragma unroll
            for (int i = 0; i < 4; i++) c[mt][nt][i] = 0.f;

#pragma unroll
    for (int kt = 0; kt < 16; kt++) {
        const int k0 = kt * 8;
        uint32_t a[2][4];
#pragma unroll
        for (int mt = 0; mt < 2; mt++) {
            int rb = wm + mt * 16;
            a[mt][0] = __float_as_uint(As[(rb + g)     * SMS + k0 + tig]);
            a[mt][1] = __float_as_uint(As[(rb + g + 8) * SMS + k0 + tig]);
            a[mt][2] = __float_as_uint(As[(rb + g)     * SMS + k0 + tig + 4]);
            a[mt][3] = __float_as_uint(As[(rb + g + 8) * SMS + k0 + tig + 4]);
        }
#pragma unroll
        for (int nt = 0; nt < 8; nt++) {
            int col = wn + nt * 8 + g;
            uint32_t b0 = __float_as_uint(Ws[(k0 + tig)     * SMS + col]);
            uint32_t b1 = __float_as_uint(Ws[(k0 + tig + 4) * SMS + col]);
#pragma unroll
            for (int mt = 0; mt < 2; mt++)
                mma_tf32(c[mt][nt], a[mt], b0, b1);
        }
    }

#pragma unroll
    for (int mt = 0; mt < 2; mt++) {
#pragma unroll
        for (int nt = 0; nt < 8; nt++) {
            int row0 = blockRow + wm + mt * 16 + g;
            int col0 = wn + nt * 8 + 2 * tig;
            if (row0 < M)
                *(__half2*)(C + (size_t)row0 * HID + col0) =
                    __floats2half2_rn(c[mt][nt][0], c[mt][nt][1]);
            int row1 = row0 + 8;
            if (row1 < M)
                *(__half2*)(C + (size_t)row1 * HID + col0) =
                    __floats2half2_rn(c[mt][nt][2], c[mt][nt][3]);
        }
    }
}

// Fused projection GEMM: C0 = A @ W[0:128], C1 = A @ W[128:256], fp16 outputs.
// Same 1xTF32 + pre-rounded staging scheme.
__global__ __launch_bounds__(512)
void gemm_proj(const float* __restrict__ A, const float* __restrict__ W,
               __half* __restrict__ C0, __half* __restrict__ C1, int M)
{
    extern __shared__ float smem[];
    float* As = smem;              // [128][SMS]
    float* Ws = smem + 128 * SMS;  // [128][WSS]

    const int tid = threadIdx.x;
    const int blockRow = blockIdx.x * 128;

#pragma unroll
    for (int t = 0; t < 8; t++) {
        int idx = tid + t * 512;
        int row = idx >> 5;
        int c4  = (idx & 31) * 4;
        int gr  = blockRow + row;
        float4 av = (gr < M) ? *(const float4*)(A + (size_t)gr * HID + c4)
                             : make_float4(0.f, 0.f, 0.f, 0.f);
        av.x = tf32r(av.x); av.y = tf32r(av.y);
        av.z = tf32r(av.z); av.w = tf32r(av.w);
        *(float4*)(As + row * SMS + c4) = av;
    }
#pragma unroll
    for (int t = 0; t < 16; t++) {
        int idx = tid + t * 512;
        int r   = idx >> 5;
        int c4  = (idx & 31) * 4;
        int k    = r & 127;
        int half = r >> 7;
        float4 wv = *(const float4*)(W + (size_t)r * HID + c4);
        wv.x = tf32r(wv.x); wv.y = tf32r(wv.y);
        wv.z = tf32r(wv.z); wv.w = tf32r(wv.w);
        *(float4*)(Ws + k * WSS + half * 128 + c4) = wv;
    }
    __syncthreads();

    const int lane = tid & 31;
    const int warp = tid >> 5;
    const int g    = lane >> 2;
    const int tig  = lane & 3;
    const int wm   = (warp >> 2) * 32;
    const int wn   = (warp & 3) * 64;

    float c[2][8][4];
#pragma unroll
    for (int mt = 0; mt < 2; mt++)
#pragma unroll
        for (int nt = 0; nt < 8; nt++)
#pragma unroll
            for (int i = 0; i < 4; i++) c[mt][nt][i] = 0.f;

#pragma unroll
    for (int kt = 0; kt < 16; kt++) {
        const int k0 = kt * 8;
        uint32_t a[2][4];
#pragma unroll
        for (int mt = 0; mt < 2; mt++) {
            int rb = wm + mt * 16;
            a[mt][0] = __float_as_uint(As[(rb + g)     * SMS + k0 + tig]);
            a[mt][1] = __float_as_uint(As[(rb + g + 8) * SMS + k0 + tig]);
            a[mt][2] = __float_as_uint(As[(rb + g)     * SMS + k0 + tig + 4]);
            a[mt][3] = __float_as_uint(As[(rb + g + 8) * SMS + k0 + tig + 4]);
        }
#pragma unroll
        for (int nt = 0; nt < 8; nt++) {
            int col = wn + nt * 8 + g;
            uint32_t b0 = __float_as_uint(Ws[(k0 + tig)     * WSS + col]);
            uint32_t b1 = __float_as_uint(Ws[(k0 + tig + 4) * WSS + col]);
#pragma unroll
            for (int mt = 0; mt < 2; mt++)
                mma_tf32(c[mt][nt], a[mt], b0, b1);
        }
    }

    __half* Cb = (wn < 128) ? C0 : C1;
    const int cbase = (wn < 128) ? wn : wn - 128;
#pragma unroll
    for (int mt = 0; mt < 2; mt++) {
#pragma unroll
        for (int nt = 0; nt < 8; nt++) {
            int row0 = blockRow + wm + mt * 16 + g;
            int col0 = cbase + nt * 8 + 2 * tig;
            if (row0 < M)
                *(__half2*)(Cb + (size_t)row0 * HID + col0) =
                    __floats2half2_rn(c[mt][nt][0], c[mt][nt][1]);
            int row1 = row0 + 8;
            if (row1 < M)
                *(__half2*)(Cb + (size_t)row1 * HID + col0) =
                    __floats2half2_rn(c[mt][nt][2], c[mt][nt][3]);
        }
    }
}

// ---------------------------------------------------------------------------
// agg[n,:] = sum_{e: dst=n} h[src_e,:]*dinv[src]*dinv[n] + h[n,:]*dinv[n]^2 + b
// fp16 gathers, fp32 (f32x2) accumulation. One warp per dst node. (R5 form.)
__global__ __launch_bounds__(256)
void gcn_aggregate(const __half* __restrict__ h, float* __restrict__ agg,
                   const int* __restrict__ rowoff, const int* __restrict__ csr_src,
                   const float* __restrict__ dinv, const float* __restrict__ bias,
                   int Nn)
{
    int lane = threadIdx.x & 31;
    int n = (blockIdx.x * blockDim.x + threadIdx.x) >> 5;
    if (n >= Nn) return;
    int c4 = lane * 4;

    float din = dinv[n];
    float wsl = din * din;
    uint2 hv = *(const uint2*)(h + (size_t)n * HID + c4);
    float2 h0 = __half22float2(*(const __half2*)&hv.x);
    float2 h1 = __half22float2(*(const __half2*)&hv.y);
    float4 bb = *(const float4*)(bias + c4);
    uint64_t acc0 = pack2(h0.x * wsl + bb.x, h0.y * wsl + bb.y);
    uint64_t acc1 = pack2(h1.x * wsl + bb.z, h1.y * wsl + bb.w);

    int beg = rowoff[n], end = rowoff[n + 1];
    for (int base = beg; base < end; base += 32) {
        int m = end - base;
        int s = 0;
        float ww = 0.f;
        if (lane < m) {
            s = __ldg(&csr_src[base + lane]);
            ww = dinv[s] * din;
        }
        int iters = min(m, 32);
#pragma unroll 4
        for (int j = 0; j < iters; j++) {
            int   sj = __shfl_sync(FULLMASK, s,  j);
            float wj = __shfl_sync(FULLMASK, ww, j);
            uint64_t wj2 = pack2(wj, wj);
            uint2 rv = *(const uint2*)(h + (size_t)sj * HID + c4);
            float2 r0 = __half22float2(*(const __half2*)&rv.x);
            float2 r1 = __half22float2(*(const __half2*)&rv.y);
            acc0 = fma2(pack2(r0.x, r0.y), wj2, acc0);
            acc1 = fma2(pack2(r1.x, r1.y), wj2, acc1);
        }
    }
    ulonglong2 outv;
    outv.x = acc0;
    outv.y = acc1;
    *(ulonglong2*)(agg + (size_t)n * HID + c4) = outv;
}

// ---------------------------------------------------------------------------
__global__ __launch_bounds__(256)
void bn_stats(const float* __restrict__ z, float* __restrict__ sum,
              float* __restrict__ sumsq, int Nn)
{
    __shared__ float sh[8][128];
    const int w  = threadIdx.x >> 5;
    const int c4 = (threadIdx.x & 31) * 4;

    float4 s = make_float4(0.f, 0.f, 0.f, 0.f);
    float4 q = make_float4(0.f, 0.f, 0.f, 0.f);
    for (int r = blockIdx.x * 8 + w; r < Nn; r += gridDim.x * 8) {
        float4 v = *(const float4*)(z + (size_t)r * HID + c4);
        s.x += v.x; s.y += v.y; s.z += v.z; s.w += v.w;
        q.x = fmaf(v.x, v.x, q.x);
        q.y = fmaf(v.y, v.y, q.y);
        q.z = fmaf(v.z, v.z, q.z);
        q.w = fmaf(v.w, v.w, q.w);
    }
    *(float4*)&sh[w][c4] = s;
    __syncthreads();
    if (threadIdx.x < 128) {
        int c = threadIdx.x;
        float t = sh[0][c] + sh[1][c] + sh[2][c] + sh[3][c]
                + sh[4][c] + sh[5][c] + sh[6][c] + sh[7][c];
        atomicAdd(&sum[c], t);
    }
    __syncthreads();
    *(float4*)&sh[w][c4] = q;
    __syncthreads();
    if (threadIdx.x < 128) {
        int c = threadIdx.x;
        float t = sh[0][c] + sh[1][c] + sh[2][c] + sh[3][c]
                + sh[4][c] + sh[5][c] + sh[6][c] + sh[7][c];
        atomicAdd(&sumsq[c], t);
    }
}

__global__ void bn_final(const float* __restrict__ sum, const float* __restrict__ sumsq,
                         const float* __restrict__ gamma, const float* __restrict__ beta,
                         float* __restrict__ scale, float* __restrict__ shift, int Nn)
{
    int i = threadIdx.x;
    if (i < HID) {
        float invN = 1.0f / (float)Nn;
        float mean = sum[i] * invN;
        float var  = sumsq[i] * invN - mean * mean;
        float sc   = gamma[i] * rsqrtf(var + 1e-5f);
        scale[i] = sc;
        shift[i] = beta[i] - mean * sc;
    }
}

// ---------------------------------------------------------------------------
// out[e] = relu(A[src] + B[dst] + edge_attr[e]@We + bm1) . Wm2 + bm2
// fp16 A/B gathers; We in registers (f32x2); per-edge partials staged in smem
// (conflict-free 33-stride), one transpose-sum per 32 edges. (R9 form.)
__global__ __launch_bounds__(256)
void edge_mlp(const __half* __restrict__ A, const __half* __restrict__ B,
              const int* __restrict__ src, const int* __restrict__ dst,
              const float* __restrict__ ea, const float* __restrict__ We,  // [16,128]
              const float* __restrict__ bm1, const float* __restrict__ Wm2,
              const float* __restrict__ bm2, float* __restrict__ out, int E)
{
    __shared__ float red[8][32][33];
    int lane  = threadIdx.x & 31;
    int wloc  = threadIdx.x >> 5;
    int warp  = (blockIdx.x * blockDim.x + threadIdx.x) >> 5;
    int nw    = (gridDim.x * blockDim.x) >> 5;
    int c4    = lane * 4;

    uint64_t wp0[16], wp1[16];
#pragma unroll
    for (int k = 0; k < 16; k++) {
        ulonglong2 wv = *(const ulonglong2*)(We + (size_t)k * HID + c4);
        wp0[k] = wv.x;
        wp1[k] = wv.y;
    }
    ulonglong2 bv2 = *(const ulonglong2*)(bm1 + c4);
    const uint64_t bias0 = bv2.x, bias1 = bv2.y;
    float4 w2 = *(const float4*)(Wm2 + c4);
    const float bm2v = __ldg(bm2);

    for (int base = warp * 32; base < E; base += nw * 32) {
        int m = min(32, E - base);
        int s = 0, d = 0;
        if (lane < m) {
            s = __ldg(&src[base + lane]);
            d = __ldg(&dst[base + lane]);
        }
        for (int j = 0; j < m; j++) {
            int sj = __shfl_sync(FULLMASK, s, j);
            int dj = __shfl_sync(FULLMASK, d, j);
            uint2 av2 = *(const uint2*)(A + (size_t)sj * HID + c4);
            uint2 bvv = *(const uint2*)(B + (size_t)dj * HID + c4);
            float2 a0 = __half22float2(*(const __half2*)&av2.x);
            float2 a1 = __half22float2(*(const __half2*)&av2.y);
            float2 b0 = __half22float2(*(const __half2*)&bvv.x);
            float2 b1 = __half22float2(*(const __half2*)&bvv.y);
            uint64_t acc0 = add2(pack2(a0.x + b0.x, a0.y + b0.y), bias0);
            uint64_t acc1 = add2(pack2(a1.x + b1.x, a1.y + b1.y), bias1);

            const float4* eap = (const float4*)(ea + (size_t)(base + j) * 16);
#pragma unroll
            for (int gq = 0; gq < 4; gq++) {
                float4 e4 = __ldg(&eap[gq]);   // uniform across warp -> broadcast
                uint64_t ex;
                ex = pack2(e4.x, e4.x);
                acc0 = fma2(wp0[gq * 4 + 0], ex, acc0);
                acc1 = fma2(wp1[gq * 4 + 0], ex, acc1);
                ex = pack2(e4.y, e4.y);
                acc0 = fma2(wp0[gq * 4 + 1], ex, acc0);
                acc1 = fma2(wp1[gq * 4 + 1], ex, acc1);
                ex = pack2(e4.z, e4.z);
                acc0 = fma2(wp0[gq * 4 + 2], ex, acc0);
                acc1 = fma2(wp1[gq * 4 + 2], ex, acc1);
                ex = pack2(e4.w, e4.w);
                acc0 = fma2(wp0[gq * 4 + 3], ex, acc0);
                acc1 = fma2(wp1[gq * 4 + 3], ex, acc1);
            }
            float f0, f1, f2, f3;
            unpack2(acc0, f0, f1);
            unpack2(acc1, f2, f3);
            f0 = fmaxf(f0, 0.f);
            f1 = fmaxf(f1, 0.f);
            f2 = fmaxf(f2, 0.f);
            f3 = fmaxf(f3, 0.f);

            red[wloc][j][lane] = f0 * w2.x + f1 * w2.y + f2 * w2.z + f3 * w2.w;
        }
        __syncwarp();
        if (lane < m) {
            const float* r = &red[wloc][lane][0];
            float t0 = 0.f, t1 = 0.f, t2 = 0.f, t3 = 0.f;
#pragma unroll
            for (int k = 0; k < 32; k += 4) {
                t0 += r[k];
                t1 += r[k + 1];
                t2 += r[k + 2];
                t3 += r[k + 3];
            }
            out[base + lane] = (t0 + t1) + (t2 + t3) + bm2v;
        }
        __syncwarp();
    }
}

// ---------------------------------------------------------------------------
extern "C" void kernel_launch(void* const* d_in, const int* in_sizes, int n_in,
                              void* d_out, int out_size)
{
    const float* x     = (const float*)d_in[0];
    const int*   ei    = (const int*)  d_in[1];
    const float* ea    = (const float*)d_in[2];
    const float* W1    = (const float*)d_in[3];
    const float* b1    = (const float*)d_in[4];
    const float* gamma = (const float*)d_in[5];
    const float* beta  = (const float*)d_in[6];
    const float* W2    = (const float*)d_in[7];
    const float* b2    = (const float*)d_in[8];
    const float* Wm1   = (const float*)d_in[9];
    const float* bm1   = (const float*)d_in[10];
    const float* Wm2   = (const float*)d_in[11];
    const float* bm2   = (const float*)d_in[12];
    float* out = (float*)d_out;

    const int Nn = in_sizes[0] / HID;
    const int E  = in_sizes[1] / 2;
    const int* src = ei;
    const int* dst = ei + E;

    float *buf0, *dinv, *sum, *sumsq, *scale, *shift;
    __half *h16, *A16, *B16;
    int *cnt, *rowoff, *cursor, *csr_src;
    cudaGetSymbolAddress((void**)&buf0,    g_buf0);
    cudaGetSymbolAddress((void**)&h16,     g_h16);
    cudaGetSymbolAddress((void**)&A16,     g_A16);
    cudaGetSymbolAddress((void**)&B16,     g_B16);
    cudaGetSymbolAddress((void**)&dinv,    g_dinv);
    cudaGetSymbolAddress((void**)&sum,     g_sum);
    cudaGetSymbolAddress((void**)&sumsq,   g_sumsq);
    cudaGetSymbolAddress((void**)&scale,   g_scale);
    cudaGetSymbolAddress((void**)&shift,   g_shift);
    cudaGetSymbolAddress((void**)&cnt,     g_cnt);
    cudaGetSymbolAddress((void**)&rowoff,  g_rowoff);
    cudaGetSymbolAddress((void**)&cursor,  g_cursor);
    cudaGetSymbolAddress((void**)&csr_src, g_csr_src);

    const int SMEM  = 2 * 128 * SMS * (int)sizeof(float);
    const int SMEMP = 128 * (SMS + WSS) * (int)sizeof(float);
    cudaFuncSetAttribute(gemm_tf32, cudaFuncAttributeMaxDynamicSharedMemorySize, SMEM);
    cudaFuncSetAttribute(gemm_proj, cudaFuncAttributeMaxDynamicSharedMemorySize, SMEMP);

    const int gN    = (Nn + 255) / 256;
    const int gE    = (E + 255) / 256;
    const int gGemm = (Nn + 127) / 128;
    const int gAgg  = (Nn * 32 + 255) / 256;

    // CSR build (by dst) + degrees
    zero_aux<<<gN, 256>>>(cnt, sum, sumsq, Nn);
    hist_dst<<<gE, 256>>>(dst, cnt, E);
    scan_offsets<<<1, 1024>>>(cnt, rowoff, cursor, dinv, Nn);
    fill_csr<<<gE, 256>>>(src, dst, cursor, csr_src, E);

    // conv1: h1 = x @ W1 (fp16) ; agg1 = CSR gather + self-loop + b1 (fp32)
    gemm_tf32<<<gGemm, 256, SMEM>>>(x, W1, h16, Nn, nullptr, nullptr);
    gcn_aggregate<<<gAgg, 256>>>(h16, buf0, rowoff, csr_src, dinv, b1, Nn);

    // batchnorm stats (apply fused into next GEMM's A staging)
    bn_stats<<<512, 256>>>(buf0, sum, sumsq, Nn);
    bn_final<<<1, 128>>>(sum, sumsq, gamma, beta, scale, shift, Nn);

    // conv2: h2 = relu(bn(agg1)) @ W2 (fp16) ; agg2 (fp32, reuse buf0)
    gemm_tf32<<<gGemm, 256, SMEM>>>(buf0, W2, h16, Nn, scale, shift);
    gcn_aggregate<<<gAgg, 256>>>(h16, buf0, rowoff, csr_src, dinv, b2, Nn);

    // fused per-node projections: A16 = z2@Wm1[0:128], B16 = z2@Wm1[128:256]
    gemm_proj<<<gGemm, 512, SMEMP>>>(buf0, Wm1, A16, B16, Nn);

    // fused edge head
    edge_mlp<<<2048, 256>>>(A16, B16, src, dst, ea, Wm1 + 256 * HID,
                            bm1, Wm2, bm2, out, E);
}

// round 11
// speedup vs baseline: 1.3151x; 1.0309x over previous
#include <cuda_runtime.h>
#include <cuda_fp16.h>
#include <cstdint>

#define MAXN 50000
#define MAXE 800000
#define HID 128
#define FULLMASK 0xffffffffu

// ---- static scratch (no allocations allowed) ----
__device__ float  g_buf0[(size_t)MAXN * HID];   // fp32 aggregate outputs
__device__ __half g_h16 [(size_t)MAXN * HID];   // fp16 h*dinv (gather target)
__device__ __half g_A16 [(size_t)MAXN * HID];   // fp16 edge-head src projection
__device__ __half g_B16 [(size_t)MAXN * HID];   // fp16 edge-head dst projection
__device__ float  g_dinv[MAXN];
__device__ float  g_sum[HID];
__device__ float  g_sumsq[HID];
__device__ float  g_scale[HID];
__device__ float  g_shift[HID];
__device__ int    g_cnt[MAXN];
__device__ int    g_rowoff[MAXN + 1];
__device__ int    g_cursor[MAXN];
__device__ int    g_csr_src[MAXE];

// ---- packed f32x2 helpers (sm_103a FFMA2 path) ----
__device__ __forceinline__ uint64_t pack2(float lo, float hi)
{
    uint64_t r;
    asm("mov.b64 %0,{%1,%2};" : "=l"(r) : "f"(lo), "f"(hi));
    return r;
}
__device__ __forceinline__ void unpack2(uint64_t v, float& lo, float& hi)
{
    asm("mov.b64 {%0,%1},%2;" : "=f"(lo), "=f"(hi) : "l"(v));
}
__device__ __forceinline__ uint64_t fma2(uint64_t a, uint64_t b, uint64_t c)
{
    uint64_t d;
    asm("fma.rn.f32x2 %0,%1,%2,%3;" : "=l"(d) : "l"(a), "l"(b), "l"(c));
    return d;
}
__device__ __forceinline__ uint64_t add2(uint64_t a, uint64_t b)
{
    uint64_t d;
    asm("add.rn.f32x2 %0,%1,%2;" : "=l"(d) : "l"(a), "l"(b));
    return d;
}

// ---------------------------------------------------------------------------
__global__ void zero_aux(int* __restrict__ cnt, float* __restrict__ sum,
                         float* __restrict__ sumsq, int n)
{
    int i = blockIdx.x * blockDim.x + threadIdx.x;
    if (i < n) cnt[i] = 0;
    if (i < HID) { sum[i] = 0.0f; sumsq[i] = 0.0f; }
}

__global__ void hist_dst(const int* __restrict__ dst, int* __restrict__ cnt, int E)
{
    int i = blockIdx.x * blockDim.x + threadIdx.x;
    if (i < E) atomicAdd(&cnt[dst[i]], 1);
}

// Single-block coalesced tiled exclusive scan. Emits rowoff, cursor, dinv.
__global__ __launch_bounds__(1024)
void scan_offsets(const int* __restrict__ cnt, int* __restrict__ rowoff,
                  int* __restrict__ cursor, float* __restrict__ dinv, int n)
{
    __shared__ int warp_sums[32];
    const int t = threadIdx.x;
    const int lane = t & 31;
    const int w = t >> 5;
    int carry = 0;

    for (int base = 0; base < n; base += 1024) {
        int i = base + t;
        int c = (i < n) ? cnt[i] : 0;
        int v = c;
#pragma unroll
        for (int o = 1; o < 32; o <<= 1) {
            int u = __shfl_up_sync(FULLMASK, v, o);
            if (lane >= o) v += u;
        }
        if (lane == 31) warp_sums[w] = v;
        __syncthreads();
        if (w == 0) {
            int sv = warp_sums[lane];
#pragma unroll
            for (int o = 1; o < 32; o <<= 1) {
                int u = __shfl_up_sync(FULLMASK, sv, o);
                if (lane >= o) sv += u;
            }
            warp_sums[lane] = sv;
        }
        __syncthreads();
        int excl = carry + (w ? warp_sums[w - 1] : 0) + v - c;
        if (i < n) {
            rowoff[i] = excl;
            cursor[i] = excl;
            dinv[i]   = rsqrtf((float)c + 1.0f);
        }
        int tile_total = warp_sums[31];
        __syncthreads();
        carry += tile_total;
    }
    if (t == 0) rowoff[n] = carry;
}

__global__ void fill_csr(const int* __restrict__ src, const int* __restrict__ dst,
                         int* __restrict__ cursor, int* __restrict__ csr_src, int E)
{
    int e = blockIdx.x * blockDim.x + threadIdx.x;
    if (e < E) {
        int d = dst[e];
        int pos = atomicAdd(&cursor[d], 1);
        csr_src[pos] = src[e];
    }
}

// ---------------------------------------------------------------------------
// 1xTF32 tensor-core GEMM. Operands pre-rounded to tf32 at smem staging;
// inner loop is pure LDS + MMA. Output fp16, optionally row-scaled (dinv).
#define SMS 136
#define WSS 264

__device__ __forceinline__ uint32_t f2tf32(float x)
{
    uint32_t r;
    asm("cvt.rna.tf32.f32 %0, %1;" : "=r"(r) : "f"(x));
    return r;
}
__device__ __forceinline__ float tf32r(float x)
{
    return __uint_as_float(f2tf32(x));
}

__device__ __forceinline__ void mma_tf32(float c[4], const uint32_t a[4],
                                         uint32_t b0, uint32_t b1)
{
    asm volatile(
        "mma.sync.aligned.m16n8k8.row.col.f32.tf32.tf32.f32 "
        "{%0,%1,%2,%3},{%4,%5,%6,%7},{%8,%9},{%0,%1,%2,%3};"
        : "+f"(c[0]), "+f"(c[1]), "+f"(c[2]), "+f"(c[3])
        : "r"(a[0]), "r"(a[1]), "r"(a[2]), "r"(a[3]), "r"(b0), "r"(b1));
}

// C16[M,128] = f(A)[M,128] @ W[128,128] * post_scale[row]
// f = optional scale/shift+relu (BN); post_scale = optional per-row multiply.
__global__ __launch_bounds__(256)
void gemm_tf32(const float* __restrict__ A, const float* __restrict__ W,
               __half* __restrict__ C, int M,
               const float* __restrict__ pre_scale,
               const float* __restrict__ pre_shift,
               const float* __restrict__ post_scale)
{
    extern __shared__ float smem[];
    float* As = smem;              // [128][SMS], tf32-rounded
    float* Ws = smem + 128 * SMS;  // [128][SMS], tf32-rounded

    const int tid = threadIdx.x;
    const int blockRow = blockIdx.x * 128;
    const bool do_pre = (pre_scale != nullptr);

#pragma unroll
    for (int t = 0; t < 16; t++) {
        int idx = tid + t * 256;
        int row = idx >> 5;
        int c4  = (idx & 31) * 4;
        int gr  = blockRow + row;
        float4 av = (gr < M) ? *(const float4*)(A + (size_t)gr * HID + c4)
                             : make_float4(0.f, 0.f, 0.f, 0.f);
        if (do_pre) {
            float4 sc = *(const float4*)(pre_scale + c4);
            float4 sh = *(const float4*)(pre_shift + c4);
            av.x = fmaxf(av.x * sc.x + sh.x, 0.f);
            av.y = fmaxf(av.y * sc.y + sh.y, 0.f);
            av.z = fmaxf(av.z * sc.z + sh.z, 0.f);
            av.w = fmaxf(av.w * sc.w + sh.w, 0.f);
        }
        av.x = tf32r(av.x); av.y = tf32r(av.y);
        av.z = tf32r(av.z); av.w = tf32r(av.w);
        *(float4*)(As + row * SMS + c4) = av;
        float4 wv = *(const float4*)(W + (size_t)row * HID + c4);
        wv.x = tf32r(wv.x); wv.y = tf32r(wv.y);
        wv.z = tf32r(wv.z); wv.w = tf32r(wv.w);
        *(float4*)(Ws + row * SMS + c4) = wv;
    }
    __syncthreads();

    const int lane = tid & 31;
    const int warp = tid >> 5;
    const int g    = lane >> 2;
    const int tig  = lane & 3;
    const int wm   = (warp >> 1) * 32;
    const int wn   = (warp & 1) * 64;

    float c[2][8][4];
#pragma unroll
    for (int mt = 0; mt < 2; mt++)
#pragma unroll
        for (int nt = 0; nt < 8; nt++)
#pragma unroll
            for (int i = 0; i < 4; i++) c[mt][nt][i] = 0.f;

#pragma unroll
    for (int kt = 0; kt < 16; kt++) {
        const int k0 = kt * 8;
        uint32_t a[2][4];
#pragma unroll
        for (int mt = 0; mt < 2; mt++) {
            int rb = wm + mt * 16;
            a[mt][0] = __float_as_uint(As[(rb + g)     * SMS + k0 + tig]);
            a[mt][1] = __float_as_uint(As[(rb + g + 8) * SMS + k0 + tig]);
            a[mt][2] = __float_as_uint(As[(rb + g)     * SMS + k0 + tig + 4]);
            a[mt][3] = __float_as_uint(As[(rb + g + 8) * SMS + k0 + tig + 4]);
        }
#pragma unroll
        for (int nt = 0; nt < 8; nt++) {
            int col = wn + nt * 8 + g;
            uint32_t b0 = __float_as_uint(Ws[(k0 + tig)     * SMS + col]);
            uint32_t b1 = __float_as_uint(Ws[(k0 + tig + 4) * SMS + col]);
#pragma unroll
            for (int mt = 0; mt < 2; mt++)
                mma_tf32(c[mt][nt], a[mt], b0, b1);
        }
    }

#pragma unroll
    for (int mt = 0; mt < 2; mt++) {
        int row0 = blockRow + wm + mt * 16 + g;
        int row1 = row0 + 8;
        float sc0 = 1.f, sc1 = 1.f;
        if (post_scale) {
            if (row0 < M) sc0 = post_scale[row0];
            if (row1 < M) sc1 = post_scale[row1];
        }
#pragma unroll
        for (int nt = 0; nt < 8; nt++) {
            int col0 = wn + nt * 8 + 2 * tig;
            if (row0 < M)
                *(__half2*)(C + (size_t)row0 * HID + col0) =
                    __floats2half2_rn(c[mt][nt][0] * sc0, c[mt][nt][1] * sc0);
            if (row1 < M)
                *(__half2*)(C + (size_t)row1 * HID + col0) =
                    __floats2half2_rn(c[mt][nt][2] * sc1, c[mt][nt][3] * sc1);
        }
    }
}

// Fused projection GEMM: C0 = A @ W[0:128], C1 = A @ W[128:256], fp16 outputs.
__global__ __launch_bounds__(512)
void gemm_proj(const float* __restrict__ A, const float* __restrict__ W,
               __half* __restrict__ C0, __half* __restrict__ C1, int M)
{
    extern __shared__ float smem[];
    float* As = smem;              // [128][SMS]
    float* Ws = smem + 128 * SMS;  // [128][WSS]

    const int tid = threadIdx.x;
    const int blockRow = blockIdx.x * 128;

#pragma unroll
    for (int t = 0; t < 8; t++) {
        int idx = tid + t * 512;
        int row = idx >> 5;
        int c4  = (idx & 31) * 4;
        int gr  = blockRow + row;
        float4 av = (gr < M) ? *(const float4*)(A + (size_t)gr * HID + c4)
                             : make_float4(0.f, 0.f, 0.f, 0.f);
        av.x = tf32r(av.x); av.y = tf32r(av.y);
        av.z = tf32r(av.z); av.w = tf32r(av.w);
        *(float4*)(As + row * SMS + c4) = av;
    }
#pragma unroll
    for (int t = 0; t < 16; t++) {
        int idx = tid + t * 512;
        int r   = idx >> 5;
        int c4  = (idx & 31) * 4;
        int k    = r & 127;
        int half = r >> 7;
        float4 wv = *(const float4*)(W + (size_t)r * HID + c4);
        wv.x = tf32r(wv.x); wv.y = tf32r(wv.y);
        wv.z = tf32r(wv.z); wv.w = tf32r(wv.w);
        *(float4*)(Ws + k * WSS + half * 128 + c4) = wv;
    }
    __syncthreads();

    const int lane = tid & 31;
    const int warp = tid >> 5;
    const int g    = lane >> 2;
    const int tig  = lane & 3;
    const int wm   = (warp >> 2) * 32;
    const int wn   = (warp & 3) * 64;

    float c[2][8][4];
#pragma unroll
    for (int mt = 0; mt < 2; mt++)
#pragma unroll
        for (int nt = 0; nt < 8; nt++)
#pragma unroll
            for (int i = 0; i < 4; i++) c[mt][nt][i] = 0.f;

#pragma unroll
    for (int kt = 0; kt < 16; kt++) {
        const int k0 = kt * 8;
        uint32_t a[2][4];
#pragma unroll
        for (int mt = 0; mt < 2; mt++) {
            int rb = wm + mt * 16;
            a[mt][0] = __float_as_uint(As[(rb + g)     * SMS + k0 + tig]);
            a[mt][1] = __float_as_uint(As[(rb + g + 8) * SMS + k0 + tig]);
            a[mt][2] = __float_as_uint(As[(rb + g)     * SMS + k0 + tig + 4]);
            a[mt][3] = __float_as_uint(As[(rb + g + 8) * SMS + k0 + tig + 4]);
        }
#pragma unroll
        for (int nt = 0; nt < 8; nt++) {
            int col = wn + nt * 8 + g;
            uint32_t b0 = __float_as_uint(Ws[(k0 + tig)     * WSS + col]);
            uint32_t b1 = __float_as_uint(Ws[(k0 + tig + 4) * WSS + col]);
#pragma unroll
            for (int mt = 0; mt < 2; mt++)
                mma_tf32(c[mt][nt], a[mt], b0, b1);
        }
    }

    __half* Cb = (wn < 128) ? C0 : C1;
    const int cbase = (wn < 128) ? wn : wn - 128;
#pragma unroll
    for (int mt = 0; mt < 2; mt++) {
#pragma unroll
        for (int nt = 0; nt < 8; nt++) {
            int row0 = blockRow + wm + mt * 16 + g;
            int col0 = cbase + nt * 8 + 2 * tig;
            if (row0 < M)
                *(__half2*)(Cb + (size_t)row0 * HID + col0) =
                    __floats2half2_rn(c[mt][nt][0], c[mt][nt][1]);
            int row1 = row0 + 8;
            if (row1 < M)
                *(__half2*)(Cb + (size_t)row1 * HID + col0) =
                    __floats2half2_rn(c[mt][nt][2], c[mt][nt][3]);
        }
    }
}

// ---------------------------------------------------------------------------
// h16 holds h' = h*dinv (prescaled in GEMM epilogue), so:
// agg[n,:] = dinv[n]*( h'[n,:] + sum_{e: dst=n} h'[src_e,:] ) + b
// Inner loop: shfl + LDG + adds only (no per-edge weights, no dinv gathers).
__global__ __launch_bounds__(256)
void gcn_aggregate(const __half* __restrict__ h, float* __restrict__ agg,
                   const int* __restrict__ rowoff, const int* __restrict__ csr_src,
                   const float* __restrict__ dinv, const float* __restrict__ bias,
                   int Nn)
{
    int lane = threadIdx.x & 31;
    int n = (blockIdx.x * blockDim.x + threadIdx.x) >> 5;
    if (n >= Nn) return;
    int c4 = lane * 4;

    uint2 hv = *(const uint2*)(h + (size_t)n * HID + c4);
    float2 h0 = __half22float2(*(const __half2*)&hv.x);
    float2 h1 = __half22float2(*(const __half2*)&hv.y);
    float a0 = h0.x, a1 = h0.y, a2 = h1.x, a3 = h1.y;

    int beg = rowoff[n], end = rowoff[n + 1];
    for (int base = beg; base < end; base += 32) {
        int m = end - base;
        int s = 0;
        if (lane < m) s = __ldg(&csr_src[base + lane]);
        int iters = min(m, 32);
#pragma unroll 8
        for (int j = 0; j < iters; j++) {
            int sj = __shfl_sync(FULLMASK, s, j);
            uint2 rv = *(const uint2*)(h + (size_t)sj * HID + c4);
            float2 r0 = __half22float2(*(const __half2*)&rv.x);
            float2 r1 = __half22float2(*(const __half2*)&rv.y);
            a0 += r0.x;
            a1 += r0.y;
            a2 += r1.x;
            a3 += r1.y;
        }
    }
    float din = dinv[n];
    float4 bb = *(const float4*)(bias + c4);
    float4 outv;
    outv.x = fmaf(a0, din, bb.x);
    outv.y = fmaf(a1, din, bb.y);
    outv.z = fmaf(a2, din, bb.z);
    outv.w = fmaf(a3, din, bb.w);
    *(float4*)(agg + (size_t)n * HID + c4) = outv;
}

// ---------------------------------------------------------------------------
__global__ __launch_bounds__(256)
void bn_stats(const float* __restrict__ z, float* __restrict__ sum,
              float* __restrict__ sumsq, int Nn)
{
    __shared__ float sh[8][128];
    const int w  = threadIdx.x >> 5;
    const int c4 = (threadIdx.x & 31) * 4;

    float4 s = make_float4(0.f, 0.f, 0.f, 0.f);
    float4 q = make_float4(0.f, 0.f, 0.f, 0.f);
    for (int r = blockIdx.x * 8 + w; r < Nn; r += gridDim.x * 8) {
        float4 v = *(const float4*)(z + (size_t)r * HID + c4);
        s.x += v.x; s.y += v.y; s.z += v.z; s.w += v.w;
        q.x = fmaf(v.x, v.x, q.x);
        q.y = fmaf(v.y, v.y, q.y);
        q.z = fmaf(v.z, v.z, q.z);
        q.w = fmaf(v.w, v.w, q.w);
    }
    *(float4*)&sh[w][c4] = s;
    __syncthreads();
    if (threadIdx.x < 128) {
        int c = threadIdx.x;
        float t = sh[0][c] + sh[1][c] + sh[2][c] + sh[3][c]
                + sh[4][c] + sh[5][c] + sh[6][c] + sh[7][c];
        atomicAdd(&sum[c], t);
    }
    __syncthreads();
    *(float4*)&sh[w][c4] = q;
    __syncthreads();
    if (threadIdx.x < 128) {
        int c = threadIdx.x;
        float t = sh[0][c] + sh[1][c] + sh[2][c] + sh[3][c]
                + sh[4][c] + sh[5][c] + sh[6][c] + sh[7][c];
        atomicAdd(&sumsq[c], t);
    }
}

__global__ void bn_final(const float* __restrict__ sum, const float* __restrict__ sumsq,
                         const float* __restrict__ gamma, const float* __restrict__ beta,
                         float* __restrict__ scale, float* __restrict__ shift, int Nn)
{
    int i = threadIdx.x;
    if (i < HID) {
        float invN = 1.0f / (float)Nn;
        float mean = sum[i] * invN;
        float var  = sumsq[i] * invN - mean * mean;
        float sc   = gamma[i] * rsqrtf(var + 1e-5f);
        scale[i] = sc;
        shift[i] = beta[i] - mean * sc;
    }
}

// ---------------------------------------------------------------------------
// out[e] = relu(A[src] + B[dst] + edge_attr[e]@We + bm1) . Wm2 + bm2
// fp16 A/B gathers; We in registers (f32x2); smem-transpose reduction. (R9/R10)
__global__ __launch_bounds__(256)
void edge_mlp(const __half* __restrict__ A, const __half* __restrict__ B,
              const int* __restrict__ src, const int* __restrict__ dst,
              const float* __restrict__ ea, const float* __restrict__ We,  // [16,128]
              const float* __restrict__ bm1, const float* __restrict__ Wm2,
              const float* __restrict__ bm2, float* __restrict__ out, int E)
{
    __shared__ float red[8][32][33];
    int lane  = threadIdx.x & 31;
    int wloc  = threadIdx.x >> 5;
    int warp  = (blockIdx.x * blockDim.x + threadIdx.x) >> 5;
    int nw    = (gridDim.x * blockDim.x) >> 5;
    int c4    = lane * 4;

    uint64_t wp0[16], wp1[16];
#pragma unroll
    for (int k = 0; k < 16; k++) {
        ulonglong2 wv = *(const ulonglong2*)(We + (size_t)k * HID + c4);
        wp0[k] = wv.x;
        wp1[k] = wv.y;
    }
    ulonglong2 bv2 = *(const ulonglong2*)(bm1 + c4);
    const uint64_t bias0 = bv2.x, bias1 = bv2.y;
    float4 w2 = *(const float4*)(Wm2 + c4);
    const float bm2v = __ldg(bm2);

    for (int base = warp * 32; base < E; base += nw * 32) {
        int m = min(32, E - base);
        int s = 0, d = 0;
        if (lane < m) {
            s = __ldg(&src[base + lane]);
            d = __ldg(&dst[base + lane]);
        }
        for (int j = 0; j < m; j++) {
            int sj = __shfl_sync(FULLMASK, s, j);
            int dj = __shfl_sync(FULLMASK, d, j);
            uint2 av2 = *(const uint2*)(A + (size_t)sj * HID + c4);
            uint2 bvv = *(const uint2*)(B + (size_t)dj * HID + c4);
            float2 a0 = __half22float2(*(const __half2*)&av2.x);
            float2 a1 = __half22float2(*(const __half2*)&av2.y);
            float2 b0 = __half22float2(*(const __half2*)&bvv.x);
            float2 b1 = __half22float2(*(const __half2*)&bvv.y);
            uint64_t acc0 = add2(pack2(a0.x + b0.x, a0.y + b0.y), bias0);
            uint64_t acc1 = add2(pack2(a1.x + b1.x, a1.y + b1.y), bias1);

            const float4* eap = (const float4*)(ea + (size_t)(base + j) * 16);
#pragma unroll
            for (int gq = 0; gq < 4; gq++) {
                float4 e4 = __ldg(&eap[gq]);   // uniform across warp -> broadcast
                uint64_t ex;
                ex = pack2(e4.x, e4.x);
                acc0 = fma2(wp0[gq * 4 + 0], ex, acc0);
                acc1 = fma2(wp1[gq * 4 + 0], ex, acc1);
                ex = pack2(e4.y, e4.y);
                acc0 = fma2(wp0[gq * 4 + 1], ex, acc0);
                acc1 = fma2(wp1[gq * 4 + 1], ex, acc1);
                ex = pack2(e4.z, e4.z);
                acc0 = fma2(wp0[gq * 4 + 2], ex, acc0);
                acc1 = fma2(wp1[gq * 4 + 2], ex, acc1);
                ex = pack2(e4.w, e4.w);
                acc0 = fma2(wp0[gq * 4 + 3], ex, acc0);
                acc1 = fma2(wp1[gq * 4 + 3], ex, acc1);
            }
            float f0, f1, f2, f3;
            unpack2(acc0, f0, f1);
            unpack2(acc1, f2, f3);
            f0 = fmaxf(f0, 0.f);
            f1 = fmaxf(f1, 0.f);
            f2 = fmaxf(f2, 0.f);
            f3 = fmaxf(f3, 0.f);

            red[wloc][j][lane] = f0 * w2.x + f1 * w2.y + f2 * w2.z + f3 * w2.w;
        }
        __syncwarp();
        if (lane < m) {
            const float* r = &red[wloc][lane][0];
            float t0 = 0.f, t1 = 0.f, t2 = 0.f, t3 = 0.f;
#pragma unroll
            for (int k = 0; k < 32; k += 4) {
                t0 += r[k];
                t1 += r[k + 1];
                t2 += r[k + 2];
                t3 += r[k + 3];
            }
            out[base + lane] = (t0 + t1) + (t2 + t3) + bm2v;
        }
        __syncwarp();
    }
}

// ---------------------------------------------------------------------------
extern "C" void kernel_launch(void* const* d_in, const int* in_sizes, int n_in,
                              void* d_out, int out_size)
{
    const float* x     = (const float*)d_in[0];
    const int*   ei    = (const int*)  d_in[1];
    const float* ea    = (const float*)d_in[2];
    const float* W1    = (const float*)d_in[3];
    const float* b1    = (const float*)d_in[4];
    const float* gamma = (const float*)d_in[5];
    const float* beta  = (const float*)d_in[6];
    const float* W2    = (const float*)d_in[7];
    const float* b2    = (const float*)d_in[8];
    const float* Wm1   = (const float*)d_in[9];
    const float* bm1   = (const float*)d_in[10];
    const float* Wm2   = (const float*)d_in[11];
    const float* bm2   = (const float*)d_in[12];
    float* out = (float*)d_out;

    const int Nn = in_sizes[0] / HID;
    const int E  = in_sizes[1] / 2;
    const int* src = ei;
    const int* dst = ei + E;

    float *buf0, *dinv, *sum, *sumsq, *scale, *shift;
    __half *h16, *A16, *B16;
    int *cnt, *rowoff, *cursor, *csr_src;
    cudaGetSymbolAddress((void**)&buf0,    g_buf0);
    cudaGetSymbolAddress((void**)&h16,     g_h16);
    cudaGetSymbolAddress((void**)&A16,     g_A16);
    cudaGetSymbolAddress((void**)&B16,     g_B16);
    cudaGetSymbolAddress((void**)&dinv,    g_dinv);
    cudaGetSymbolAddress((void**)&sum,     g_sum);
    cudaGetSymbolAddress((void**)&sumsq,   g_sumsq);
    cudaGetSymbolAddress((void**)&scale,   g_scale);
    cudaGetSymbolAddress((void**)&shift,   g_shift);
    cudaGetSymbolAddress((void**)&cnt,     g_cnt);
    cudaGetSymbolAddress((void**)&rowoff,  g_rowoff);
    cudaGetSymbolAddress((void**)&cursor,  g_cursor);
    cudaGetSymbolAddress((void**)&csr_src, g_csr_src);

    const int SMEM  = 2 * 128 * SMS * (int)sizeof(float);
    const int SMEMP = 128 * (SMS + WSS) * (int)sizeof(float);
    cudaFuncSetAttribute(gemm_tf32, cudaFuncAttributeMaxDynamicSharedMemorySize, SMEM);
    cudaFuncSetAttribute(gemm_proj, cudaFuncAttributeMaxDynamicSharedMemorySize, SMEMP);

    const int gN    = (Nn + 255) / 256;
    const int gE    = (E + 255) / 256;
    const int gGemm = (Nn + 127) / 128;
    const int gAgg  = (Nn * 32 + 255) / 256;

    // CSR build + conv1 GEMM interleaved. gemm1 placed at stream index 3
    // (the launch ncu's fixed -s/-c window profiles) for visibility.
    zero_aux<<<gN, 256>>>(cnt, sum, sumsq, Nn);
    hist_dst<<<gE, 256>>>(dst, cnt, E);
    scan_offsets<<<1, 1024>>>(cnt, rowoff, cursor, dinv, Nn);
    gemm_tf32<<<gGemm, 256, SMEM>>>(x, W1, h16, Nn, nullptr, nullptr, dinv);
    fill_csr<<<gE, 256>>>(src, dst, cursor, csr_src, E);

    // conv1 aggregate (h16 is prescaled by dinv)
    gcn_aggregate<<<gAgg, 256>>>(h16, buf0, rowoff, csr_src, dinv, b1, Nn);

    // batchnorm stats (apply fused into next GEMM's A staging)
    bn_stats<<<512, 256>>>(buf0, sum, sumsq, Nn);
    bn_final<<<1, 128>>>(sum, sumsq, gamma, beta, scale, shift, Nn);

    // conv2: h2' = (relu(bn(agg1)) @ W2) * dinv ; agg2 (fp32, reuse buf0)
    gemm_tf32<<<gGemm, 256, SMEM>>>(buf0, W2, h16, Nn, scale, shift, dinv);
    gcn_aggregate<<<gAgg, 256>>>(h16, buf0, rowoff, csr_src, dinv, b2, Nn);

    // fused per-node projections: A16 = z2@Wm1[0:128], B16 = z2@Wm1[128:256]
    gemm_proj<<<gGemm, 512, SMEMP>>>(buf0, Wm1, A16, B16, Nn);

    // fused edge head
    edge_mlp<<<2048, 256>>>(A16, B16, src, dst, ea, Wm1 + 256 * HID,
                            bm1, Wm2, bm2, out, E);
}